// round 11
// baseline (speedup 1.0000x reference)
#include <cuda_runtime.h>
#include <cuda_bf16.h>
#include <cstdint>

#define HF 128
#define LSEQ 2048
#define BATCH 128
#define CHUNK 512
#define TILE_M 32
#define NTILES (CHUNK / TILE_M)
#define THREADS 256

#define ASTRIDE 136    // A row stride in bf16 (272B -> ldmatrix conflict-free)
#define B4STRIDE 130   // B image row stride in uint4 (conflict-free LDS.128)

// smem byte offsets
#define SM_B4    0
#define SM_A     66560
#define ABUF_SZ  17408     // one buffer: Ahi 8704 + Alo 8704 (32 rows x 136 bf16)
#define SM_GEO   101376
#define SM_SEQ   105472
#define SM_RED   107552
#define SM_TOTAL 107616

// ---------------- helpers ----------------
__device__ __forceinline__ uint32_t smem_u32(const void* p) {
    uint32_t a;
    asm("{ .reg .u64 t; cvta.to.shared.u64 t, %1; cvt.u32.u64 %0, t; }" : "=r"(a) : "l"(p));
    return a;
}
__device__ __forceinline__ void ldmatrix4(uint32_t a[4], uint32_t addr) {
    asm volatile("ldmatrix.sync.aligned.m8n8.x4.shared.b16 {%0,%1,%2,%3}, [%4];"
                 : "=r"(a[0]), "=r"(a[1]), "=r"(a[2]), "=r"(a[3]) : "r"(addr));
}
__device__ __forceinline__ void mma_bf16(float c[4], const uint32_t a[4],
                                         uint32_t b0, uint32_t b1) {
    asm volatile("mma.sync.aligned.m16n8k16.row.col.f32.bf16.bf16.f32 "
                 "{%0,%1,%2,%3}, {%4,%5,%6,%7}, {%8,%9}, {%0,%1,%2,%3};"
                 : "+f"(c[0]), "+f"(c[1]), "+f"(c[2]), "+f"(c[3])
                 : "r"(a[0]), "r"(a[1]), "r"(a[2]), "r"(a[3]), "r"(b0), "r"(b1));
}

// ---------------- globals ----------------
__device__ float g_P[9 * 20 * HF];
__device__ uint4 g_B4[3][32 * B4STRIDE];   // interleaved {bh0,bh1,bl0,bl1} frag image

__global__ void zero_out_kernel(float* out) { out[threadIdx.x] = 0.f; }

__global__ void precompute_P_kernel(const float* __restrict__ emb,
                                    const float* __restrict__ W1_0,
                                    const float* __restrict__ W1_1,
                                    const float* __restrict__ W1_2) {
    int aa = blockIdx.x, gk = blockIdx.y, j = threadIdx.x;
    const float* W1; int k, G;
    if (gk < 2)      { W1 = W1_0; k = gk;     G = 1; }
    else if (gk < 5) { W1 = W1_1; k = gk - 2; G = 1; }
    else             { W1 = W1_2; k = gk - 5; G = 2; }
    float s = 0.f;
    #pragma unroll
    for (int c = 0; c < 16; c++)
        s += emb[aa * 16 + c] * W1[(G + k * 16 + c) * HF + j];
    g_P[(gk * 20 + aa) * HF + j] = s;
}

// Per (kt, tig, n): b0 covers k rows {16kt+2tig, +1}, b1 covers {16kt+8+2tig, +1}.
__global__ void precompute_B4_kernel(const float* __restrict__ W2_0,
                                     const float* __restrict__ W2_1,
                                     const float* __restrict__ W2_2) {
    int n = blockIdx.x, type = blockIdx.y, t = threadIdx.x;  // t 0..31
    const float* W2 = (type == 0) ? W2_0 : (type == 1) ? W2_1 : W2_2;
    int kt = t >> 2, tig = t & 3;
    int kA = 16 * kt + 2 * tig;
    int kB = kA + 8;
    float w00 = W2[kA * HF + n],       w01 = W2[(kA + 1) * HF + n];
    float w10 = W2[kB * HF + n],       w11 = W2[(kB + 1) * HF + n];
    __nv_bfloat16 h00 = __float2bfloat16(w00), h01 = __float2bfloat16(w01);
    __nv_bfloat16 h10 = __float2bfloat16(w10), h11 = __float2bfloat16(w11);
    __nv_bfloat16 l00 = __float2bfloat16(w00 - __bfloat162float(h00));
    __nv_bfloat16 l01 = __float2bfloat16(w01 - __bfloat162float(h01));
    __nv_bfloat16 l10 = __float2bfloat16(w10 - __bfloat162float(h10));
    __nv_bfloat16 l11 = __float2bfloat16(w11 - __bfloat162float(h11));
    uint4 v;
    v.x = (uint32_t)__bfloat16_as_ushort(h00) | ((uint32_t)__bfloat16_as_ushort(h01) << 16);
    v.y = (uint32_t)__bfloat16_as_ushort(h10) | ((uint32_t)__bfloat16_as_ushort(h11) << 16);
    v.z = (uint32_t)__bfloat16_as_ushort(l00) | ((uint32_t)__bfloat16_as_ushort(l01) << 16);
    v.w = (uint32_t)__bfloat16_as_ushort(l10) | ((uint32_t)__bfloat16_as_ushort(l11) << 16);
    g_B4[type][t * B4STRIDE + n] = v;
}

// ---------------- main fused kernel ----------------
template <int TYPE, int G, int NE>
__device__ __forceinline__ void run_type(
        char* sm, uint32_t smb,
        const float* __restrict__ R, const int* __restrict__ seq,
        const float* __restrict__ Pg,
        const float* __restrict__ W1, const float* __restrict__ b1,
        const float* __restrict__ b2, const float* __restrict__ W3,
        const float* __restrict__ b3,
        const uint4* __restrict__ B4_g,
        float* __restrict__ out) {
    constexpr int Nelem = LSEQ - 1 - TYPE;

    int*   s_seq = (int*)(sm + SM_SEQ);
    float* s_geo = (float*)(sm + SM_GEO);
    float* s_red = (float*)(sm + SM_RED);
    const uint4* s_B4 = (const uint4*)(sm + SM_B4);

    const int tid  = threadIdx.x;
    const int lane = tid & 31;
    const int wid  = tid >> 5;
    const int jcol = tid & 127;
    const int half = tid >> 7;
    const int mw   = wid >> 2;       // 0..1 : M-half (16 rows each)
    const int nw   = wid & 3;        // 0..3 : N-quarter
    const int gid  = lane >> 2;      // 0..7
    const int tig  = lane & 3;       // 0..3
    const int b    = blockIdx.y;
    const int cstart = blockIdx.x * CHUNK;

    // ---- B image -> smem ----
    {
        uint4* db = (uint4*)(sm + SM_B4);
        for (int t = tid; t < 32 * B4STRIDE; t += THREADS) db[t] = B4_g[t];
    }
    for (int t = tid; t < CHUNK + 4; t += THREADS) {
        int idx = cstart + t;
        if (idx >= LSEQ) idx = LSEQ - 1;
        s_seq[t] = seq[b * LSEQ + idx];
    }
    const float b1j  = b1[jcol];
    const float w1g0 = W1[jcol];
    const float w1g1 = (G == 2) ? W1[HF + jcol] : 0.f;
    const float b3s  = b3[0];

    // per-thread epilogue coefficients for its 8 columns
    float b2v[8], w3v[8];
    #pragma unroll
    for (int nt = 0; nt < 4; nt++) {
        #pragma unroll
        for (int u = 0; u < 2; u++) {
            int c = nw * 32 + nt * 8 + tig * 2 + u;
            b2v[nt * 2 + u] = __ldg(&b2[c]);
            w3v[nt * 2 + u] = __ldg(&W3[c]);
        }
    }

    // ---- geometry for the whole 512-elem chunk ----
    const float* Rb = R + (size_t)b * LSEQ * 3;
    for (int t = tid; t < CHUNK; t += THREADS) {
        int i = cstart + t;
        if (i < Nelem) {
            if (TYPE == 0) {
                float dx = __ldg(&Rb[(i + 1) * 3 + 0]) - __ldg(&Rb[i * 3 + 0]);
                float dy = __ldg(&Rb[(i + 1) * 3 + 1]) - __ldg(&Rb[i * 3 + 1]);
                float dz = __ldg(&Rb[(i + 1) * 3 + 2]) - __ldg(&Rb[i * 3 + 2]);
                s_geo[t] = sqrtf(dx * dx + dy * dy + dz * dz);
            } else if (TYPE == 1) {
                float ax = __ldg(&Rb[i * 3 + 0]), ay = __ldg(&Rb[i * 3 + 1]), az = __ldg(&Rb[i * 3 + 2]);
                float bx = __ldg(&Rb[(i + 1) * 3 + 0]), by = __ldg(&Rb[(i + 1) * 3 + 1]), bz = __ldg(&Rb[(i + 1) * 3 + 2]);
                float cx = __ldg(&Rb[(i + 2) * 3 + 0]), cy = __ldg(&Rb[(i + 2) * 3 + 1]), cz = __ldg(&Rb[(i + 2) * 3 + 2]);
                float ux = ax - bx, uy = ay - by, uz = az - bz;
                float vx = cx - bx, vy = cy - by, vz = cz - bz;
                float num = ux * vx + uy * vy + uz * vz;
                float den = sqrtf((ux * ux + uy * uy + uz * uz) * (vx * vx + vy * vy + vz * vz));
                float c = num / den;
                s_geo[t] = fminf(1.f, fmaxf(-1.f, c));
            } else {
                float p0x = __ldg(&Rb[i * 3 + 0]), p0y = __ldg(&Rb[i * 3 + 1]), p0z = __ldg(&Rb[i * 3 + 2]);
                float p1x = __ldg(&Rb[(i + 1) * 3 + 0]), p1y = __ldg(&Rb[(i + 1) * 3 + 1]), p1z = __ldg(&Rb[(i + 1) * 3 + 2]);
                float p2x = __ldg(&Rb[(i + 2) * 3 + 0]), p2y = __ldg(&Rb[(i + 2) * 3 + 1]), p2z = __ldg(&Rb[(i + 2) * 3 + 2]);
                float p3x = __ldg(&Rb[(i + 3) * 3 + 0]), p3y = __ldg(&Rb[(i + 3) * 3 + 1]), p3z = __ldg(&Rb[(i + 3) * 3 + 2]);
                float b1x = p1x - p0x, b1y = p1y - p0y, b1z = p1z - p0z;
                float b2x = p2x - p1x, b2y = p2y - p1y, b2z = p2z - p1z;
                float b3x = p3x - p2x, b3y = p3y - p2y, b3z = p3z - p2z;
                float n1x = b1y * b2z - b1z * b2y, n1y = b1z * b2x - b1x * b2z, n1z = b1x * b2y - b1y * b2x;
                float n2x = b2y * b3z - b2z * b3y, n2y = b2z * b3x - b2x * b3z, n2z = b2x * b3y - b2y * b3x;
                float inv = rsqrtf(b2x * b2x + b2y * b2y + b2z * b2z);
                float ux = b2x * inv, uy = b2y * inv, uz = b2z * inv;
                float m1x = n1y * uz - n1z * uy, m1y = n1z * ux - n1x * uz, m1z = n1x * uy - n1y * ux;
                float yv = m1x * n2x + m1y * n2y + m1z * n2z;
                float xv = n1x * n2x + n1y * n2y + n1z * n2z;
                float rn = rsqrtf(xv * xv + yv * yv);
                s_geo[t * 2 + 0] = yv * rn;
                s_geo[t * 2 + 1] = xv * rn;
            }
        } else {
            if (G == 1) s_geo[t] = 0.f;
            else { s_geo[t * 2 + 0] = 0.f; s_geo[t * 2 + 1] = 0.f; }
        }
    }
    __syncthreads();

    // ldmatrix per-thread base byte offset into an A buffer
    const uint32_t a_off = (uint32_t)((mw * 16 + (lane & 15)) * ASTRIDE + (lane >> 4) * 8) * 2;

    // ---- layer1 producer for one tile into buffer `buf` ----
    auto layer1 = [&](int tile, int buf) {
        __nv_bfloat16* aHi = (__nv_bfloat16*)(sm + SM_A + buf * ABUF_SZ);
        __nv_bfloat16* aLo = (__nv_bfloat16*)(sm + SM_A + buf * ABUF_SZ + 8704);
        const int li0 = tile * TILE_M + half * 16;
        #pragma unroll 4
        for (int e = 0; e < 16; e++) {
            const int li = li0 + e;
            float acc = b1j;
            if (G == 2) {
                float2 sc = ((const float2*)s_geo)[li];
                acc = fmaf(sc.x, w1g0, fmaf(sc.y, w1g1, acc));
            } else {
                acc = fmaf(s_geo[li], w1g0, acc);
            }
            #pragma unroll
            for (int k = 0; k < NE; k++)
                acc += __ldg(&Pg[(k * 20 + s_seq[li + k]) * HF + jcol]);
            float h = fmaxf(acc, 0.f);
            __nv_bfloat16 hb = __float2bfloat16(h);
            float lf = h - __bfloat162float(hb);
            int row = half * 16 + e;
            aHi[row * ASTRIDE + jcol] = hb;
            aLo[row * ASTRIDE + jcol] = __float2bfloat16(lf);
        }
    };

    float thread_sum = 0.f;

    // prologue: fill buffer 0 with tile 0
    layer1(0, 0);
    __syncthreads();

    for (int tile = 0; tile < NTILES; tile++) {
        const int cur = tile & 1;

        // ---- produce next tile's A into the other buffer (overlaps MMA) ----
        if (tile + 1 < NTILES) layer1(tile + 1, cur ^ 1);

        // ---- MMA on current buffer: C = Ahi*Bhi + Ahi*Blo + Alo*Bhi ----
        float c[4][4];
        #pragma unroll
        for (int nt = 0; nt < 4; nt++)
            #pragma unroll
            for (int q = 0; q < 4; q++) c[nt][q] = 0.f;

        const uint32_t abase = smb + SM_A + (uint32_t)cur * ABUF_SZ + a_off;
        #pragma unroll
        for (int kt = 0; kt < 8; kt++) {
            uint4 bb[4];
            #pragma unroll
            for (int nt = 0; nt < 4; nt++)
                bb[nt] = s_B4[(kt * 4 + tig) * B4STRIDE + nw * 32 + nt * 8 + gid];
            uint32_t ah[4], al[4];
            ldmatrix4(ah, abase + (uint32_t)(kt * 32));
            ldmatrix4(al, abase + (uint32_t)(8704 + kt * 32));
            #pragma unroll
            for (int nt = 0; nt < 4; nt++) {
                mma_bf16(c[nt], ah, bb[nt].x, bb[nt].y);
                mma_bf16(c[nt], ah, bb[nt].z, bb[nt].w);
                mma_bf16(c[nt], al, bb[nt].x, bb[nt].y);
            }
        }

        // ---- epilogue: sum relu(D + b2)*w3 over valid rows ----
        {
            const int e0 = cstart + tile * TILE_M + mw * 16;
            const bool v0 = (e0 + gid) < Nelem;
            const bool v1 = (e0 + gid + 8) < Nelem;
            float p0 = 0.f, p1 = 0.f;
            #pragma unroll
            for (int nt = 0; nt < 4; nt++) {
                p0 += fmaxf(c[nt][0] + b2v[nt * 2 + 0], 0.f) * w3v[nt * 2 + 0]
                    + fmaxf(c[nt][1] + b2v[nt * 2 + 1], 0.f) * w3v[nt * 2 + 1];
                p1 += fmaxf(c[nt][2] + b2v[nt * 2 + 0], 0.f) * w3v[nt * 2 + 0]
                    + fmaxf(c[nt][3] + b2v[nt * 2 + 1], 0.f) * w3v[nt * 2 + 1];
            }
            thread_sum += (v0 ? p0 : 0.f) + (v1 ? p1 : 0.f);
        }
        __syncthreads();   // next-tile buffer complete; current buffer free
    }

    // ---- final reduction ----
    #pragma unroll
    for (int off = 16; off; off >>= 1)
        thread_sum += __shfl_xor_sync(0xffffffffu, thread_sum, off);
    if (lane == 0) s_red[wid] = thread_sum;
    __syncthreads();
    if (tid == 0) {
        int count = Nelem - cstart;
        if (count > CHUNK) count = CHUNK;
        float total = 0.f;
        #pragma unroll
        for (int w = 0; w < 8; w++) total += s_red[w];
        atomicAdd(&out[b], total + (float)count * b3s);
    }
}

__global__ __launch_bounds__(THREADS, 2)
void fused_energy_kernel(const float* __restrict__ R, const int* __restrict__ seq,
                         const float* fl_W1, const float* fl_b1, const float* fl_b2,
                         const float* fl_W3, const float* fl_b3,
                         const float* ft_W1, const float* ft_b1, const float* ft_b2,
                         const float* ft_W3, const float* ft_b3,
                         const float* fp_W1, const float* fp_b1, const float* fp_b2,
                         const float* fp_W3, const float* fp_b3,
                         float* __restrict__ out) {
    extern __shared__ char sm[];
    uint32_t smb = smem_u32(sm);
    if (blockIdx.z == 0) {
        run_type<0, 1, 2>(sm, smb, R, seq, g_P + 0 * 20 * HF,
                          fl_W1, fl_b1, fl_b2, fl_W3, fl_b3, g_B4[0], out);
    } else if (blockIdx.z == 1) {
        run_type<1, 1, 3>(sm, smb, R, seq, g_P + 2 * 20 * HF,
                          ft_W1, ft_b1, ft_b2, ft_W3, ft_b3, g_B4[1], out);
    } else {
        run_type<2, 2, 4>(sm, smb, R, seq, g_P + 5 * 20 * HF,
                          fp_W1, fp_b1, fp_b2, fp_W3, fp_b3, g_B4[2], out);
    }
}

extern "C" void kernel_launch(void* const* d_in, const int* in_sizes, int n_in,
                              void* d_out, int out_size) {
    const float* R   = (const float*)d_in[0];
    const int*   seq = (const int*)d_in[1];
    const float* emb = (const float*)d_in[2];
    const float* fl_W1 = (const float*)d_in[3];
    const float* fl_b1 = (const float*)d_in[4];
    const float* fl_W2 = (const float*)d_in[5];
    const float* fl_b2 = (const float*)d_in[6];
    const float* fl_W3 = (const float*)d_in[7];
    const float* fl_b3 = (const float*)d_in[8];
    const float* ft_W1 = (const float*)d_in[9];
    const float* ft_b1 = (const float*)d_in[10];
    const float* ft_W2 = (const float*)d_in[11];
    const float* ft_b2 = (const float*)d_in[12];
    const float* ft_W3 = (const float*)d_in[13];
    const float* ft_b3 = (const float*)d_in[14];
    const float* fp_W1 = (const float*)d_in[15];
    const float* fp_b1 = (const float*)d_in[16];
    const float* fp_W2 = (const float*)d_in[17];
    const float* fp_b2 = (const float*)d_in[18];
    const float* fp_W3 = (const float*)d_in[19];
    const float* fp_b3 = (const float*)d_in[20];
    float* out = (float*)d_out;

    cudaFuncSetAttribute(fused_energy_kernel,
                         cudaFuncAttributeMaxDynamicSharedMemorySize, SM_TOTAL);

    zero_out_kernel<<<1, 128>>>(out);

    dim3 pgrid(20, 9);
    precompute_P_kernel<<<pgrid, 128>>>(emb, fl_W1, ft_W1, fp_W1);
    dim3 bgrid(128, 3);
    precompute_B4_kernel<<<bgrid, 32>>>(fl_W2, ft_W2, fp_W2);

    dim3 grid(LSEQ / CHUNK, BATCH, 3);  // 4 x 128 x 3
    fused_energy_kernel<<<grid, THREADS, SM_TOTAL>>>(R, seq,
        fl_W1, fl_b1, fl_b2, fl_W3, fl_b3,
        ft_W1, ft_b1, ft_b2, ft_W3, ft_b3,
        fp_W1, fp_b1, fp_b2, fp_W3, fp_b3, out);
}

// round 12
// speedup vs baseline: 1.6011x; 1.6011x over previous
#include <cuda_runtime.h>
#include <cuda_bf16.h>
#include <cstdint>

#define HF 128
#define LSEQ 2048
#define BATCH 128
#define CHUNK 704
#define TILE_M 64
#define NTILES 11
#define THREADS 256

#define ASTRIDE 136    // A row stride in bf16 (272B -> ldmatrix conflict-free)
#define B4STRIDE 130   // B image row stride in uint4 (conflict-free LDS.128)

// smem byte offsets
#define SM_B4    0
#define SM_A     66560            // Ahi 17408 | Alo 17408
#define SM_GEO   101376           // 704*2*4 = 5632
#define SM_SEQ   107008           // 708*4 = 2832
#define SM_RED   109840
#define SM_TOTAL 109904

// ---------------- helpers ----------------
__device__ __forceinline__ uint32_t smem_u32(const void* p) {
    uint32_t a;
    asm("{ .reg .u64 t; cvta.to.shared.u64 t, %1; cvt.u32.u64 %0, t; }" : "=r"(a) : "l"(p));
    return a;
}
__device__ __forceinline__ void ldmatrix4(uint32_t a[4], uint32_t addr) {
    asm volatile("ldmatrix.sync.aligned.m8n8.x4.shared.b16 {%0,%1,%2,%3}, [%4];"
                 : "=r"(a[0]), "=r"(a[1]), "=r"(a[2]), "=r"(a[3]) : "r"(addr));
}
__device__ __forceinline__ void mma_bf16(float c[4], const uint32_t a[4],
                                         uint32_t b0, uint32_t b1) {
    asm volatile("mma.sync.aligned.m16n8k16.row.col.f32.bf16.bf16.f32 "
                 "{%0,%1,%2,%3}, {%4,%5,%6,%7}, {%8,%9}, {%0,%1,%2,%3};"
                 : "+f"(c[0]), "+f"(c[1]), "+f"(c[2]), "+f"(c[3])
                 : "r"(a[0]), "r"(a[1]), "r"(a[2]), "r"(a[3]), "r"(b0), "r"(b1));
}

// ---------------- globals ----------------
__device__ float g_P[9 * 20 * HF];
__device__ uint4 g_B4[3][32 * B4STRIDE];   // interleaved {bh0,bh1,bl0,bl1} frag image

__global__ void zero_out_kernel(float* out) { out[threadIdx.x] = 0.f; }

__global__ void precompute_P_kernel(const float* __restrict__ emb,
                                    const float* __restrict__ W1_0,
                                    const float* __restrict__ W1_1,
                                    const float* __restrict__ W1_2) {
    int aa = blockIdx.x, gk = blockIdx.y, j = threadIdx.x;
    const float* W1; int k, G;
    if (gk < 2)      { W1 = W1_0; k = gk;     G = 1; }
    else if (gk < 5) { W1 = W1_1; k = gk - 2; G = 1; }
    else             { W1 = W1_2; k = gk - 5; G = 2; }
    float s = 0.f;
    #pragma unroll
    for (int c = 0; c < 16; c++)
        s += emb[aa * 16 + c] * W1[(G + k * 16 + c) * HF + j];
    g_P[(gk * 20 + aa) * HF + j] = s;
}

// Per (kt, tig, n): b0 covers k rows {16kt+2tig, +1}, b1 covers {16kt+8+2tig, +1}.
__global__ void precompute_B4_kernel(const float* __restrict__ W2_0,
                                     const float* __restrict__ W2_1,
                                     const float* __restrict__ W2_2) {
    int n = blockIdx.x, type = blockIdx.y, t = threadIdx.x;  // t 0..31
    const float* W2 = (type == 0) ? W2_0 : (type == 1) ? W2_1 : W2_2;
    int kt = t >> 2, tig = t & 3;
    int kA = 16 * kt + 2 * tig;
    int kB = kA + 8;
    float w00 = W2[kA * HF + n],  w01 = W2[(kA + 1) * HF + n];
    float w10 = W2[kB * HF + n],  w11 = W2[(kB + 1) * HF + n];
    __nv_bfloat16 h00 = __float2bfloat16(w00), h01 = __float2bfloat16(w01);
    __nv_bfloat16 h10 = __float2bfloat16(w10), h11 = __float2bfloat16(w11);
    __nv_bfloat16 l00 = __float2bfloat16(w00 - __bfloat162float(h00));
    __nv_bfloat16 l01 = __float2bfloat16(w01 - __bfloat162float(h01));
    __nv_bfloat16 l10 = __float2bfloat16(w10 - __bfloat162float(h10));
    __nv_bfloat16 l11 = __float2bfloat16(w11 - __bfloat162float(h11));
    uint4 v;
    v.x = (uint32_t)__bfloat16_as_ushort(h00) | ((uint32_t)__bfloat16_as_ushort(h01) << 16);
    v.y = (uint32_t)__bfloat16_as_ushort(h10) | ((uint32_t)__bfloat16_as_ushort(h11) << 16);
    v.z = (uint32_t)__bfloat16_as_ushort(l00) | ((uint32_t)__bfloat16_as_ushort(l01) << 16);
    v.w = (uint32_t)__bfloat16_as_ushort(l10) | ((uint32_t)__bfloat16_as_ushort(l11) << 16);
    g_B4[type][t * B4STRIDE + n] = v;
}

// ---------------- main fused kernel ----------------
template <int TYPE, int G, int NE>
__device__ __forceinline__ void run_type(
        char* sm, uint32_t smb,
        const float* __restrict__ R, const int* __restrict__ seq,
        const float* __restrict__ Pg,
        const float* __restrict__ W1, const float* __restrict__ b1,
        const float* __restrict__ b2, const float* __restrict__ W3,
        const float* __restrict__ b3,
        const uint4* __restrict__ B4_g,
        float* __restrict__ out) {
    constexpr int Nelem = LSEQ - 1 - TYPE;

    int*   s_seq = (int*)(sm + SM_SEQ);
    float* s_geo = (float*)(sm + SM_GEO);
    float* s_red = (float*)(sm + SM_RED);
    __nv_bfloat16* s_Ahi = (__nv_bfloat16*)(sm + SM_A);
    __nv_bfloat16* s_Alo = (__nv_bfloat16*)(sm + SM_A + 17408);
    const uint4* s_B4 = (const uint4*)(sm + SM_B4);

    const int tid  = threadIdx.x;
    const int lane = tid & 31;
    const int wid  = tid >> 5;
    const int jcol = tid & 127;
    const int half = tid >> 7;
    const int mw   = wid >> 2;       // 0..1 : M-half (32 rows each)
    const int nw   = wid & 3;        // 0..3 : N-quarter
    const int gid  = lane >> 2;      // 0..7
    const int tig  = lane & 3;       // 0..3
    const int b    = blockIdx.y;
    const int cstart = blockIdx.x * CHUNK;

    // ---- B image -> smem ----
    {
        uint4* db = (uint4*)(sm + SM_B4);
        for (int t = tid; t < 32 * B4STRIDE; t += THREADS) db[t] = B4_g[t];
    }
    for (int t = tid; t < CHUNK + 4; t += THREADS) {
        int idx = cstart + t;
        if (idx >= LSEQ) idx = LSEQ - 1;
        s_seq[t] = seq[b * LSEQ + idx];
    }
    const float b1j  = b1[jcol];
    const float w1g0 = W1[jcol];
    const float w1g1 = (G == 2) ? W1[HF + jcol] : 0.f;
    const float b3s  = b3[0];

    // per-thread epilogue coefficients for its 8 columns
    float b2v[8], w3v[8];
    #pragma unroll
    for (int nt = 0; nt < 4; nt++) {
        #pragma unroll
        for (int u = 0; u < 2; u++) {
            int c = nw * 32 + nt * 8 + tig * 2 + u;
            b2v[nt * 2 + u] = __ldg(&b2[c]);
            w3v[nt * 2 + u] = __ldg(&W3[c]);
        }
    }

    // ---- geometry for the whole chunk ----
    const float* Rb = R + (size_t)b * LSEQ * 3;
    for (int t = tid; t < CHUNK; t += THREADS) {
        int i = cstart + t;
        if (i < Nelem) {
            if (TYPE == 0) {
                float dx = __ldg(&Rb[(i + 1) * 3 + 0]) - __ldg(&Rb[i * 3 + 0]);
                float dy = __ldg(&Rb[(i + 1) * 3 + 1]) - __ldg(&Rb[i * 3 + 1]);
                float dz = __ldg(&Rb[(i + 1) * 3 + 2]) - __ldg(&Rb[i * 3 + 2]);
                s_geo[t] = sqrtf(dx * dx + dy * dy + dz * dz);
            } else if (TYPE == 1) {
                float ax = __ldg(&Rb[i * 3 + 0]), ay = __ldg(&Rb[i * 3 + 1]), az = __ldg(&Rb[i * 3 + 2]);
                float bx = __ldg(&Rb[(i + 1) * 3 + 0]), by = __ldg(&Rb[(i + 1) * 3 + 1]), bz = __ldg(&Rb[(i + 1) * 3 + 2]);
                float cx = __ldg(&Rb[(i + 2) * 3 + 0]), cy = __ldg(&Rb[(i + 2) * 3 + 1]), cz = __ldg(&Rb[(i + 2) * 3 + 2]);
                float ux = ax - bx, uy = ay - by, uz = az - bz;
                float vx = cx - bx, vy = cy - by, vz = cz - bz;
                float num = ux * vx + uy * vy + uz * vz;
                float den = sqrtf((ux * ux + uy * uy + uz * uz) * (vx * vx + vy * vy + vz * vz));
                float c = num / den;
                s_geo[t] = fminf(1.f, fmaxf(-1.f, c));
            } else {
                float p0x = __ldg(&Rb[i * 3 + 0]), p0y = __ldg(&Rb[i * 3 + 1]), p0z = __ldg(&Rb[i * 3 + 2]);
                float p1x = __ldg(&Rb[(i + 1) * 3 + 0]), p1y = __ldg(&Rb[(i + 1) * 3 + 1]), p1z = __ldg(&Rb[(i + 1) * 3 + 2]);
                float p2x = __ldg(&Rb[(i + 2) * 3 + 0]), p2y = __ldg(&Rb[(i + 2) * 3 + 1]), p2z = __ldg(&Rb[(i + 2) * 3 + 2]);
                float p3x = __ldg(&Rb[(i + 3) * 3 + 0]), p3y = __ldg(&Rb[(i + 3) * 3 + 1]), p3z = __ldg(&Rb[(i + 3) * 3 + 2]);
                float b1x = p1x - p0x, b1y = p1y - p0y, b1z = p1z - p0z;
                float b2x = p2x - p1x, b2y = p2y - p1y, b2z = p2z - p1z;
                float b3x = p3x - p2x, b3y = p3y - p2y, b3z = p3z - p2z;
                float n1x = b1y * b2z - b1z * b2y, n1y = b1z * b2x - b1x * b2z, n1z = b1x * b2y - b1y * b2x;
                float n2x = b2y * b3z - b2z * b3y, n2y = b2z * b3x - b2x * b3z, n2z = b2x * b3y - b2y * b3x;
                float inv = rsqrtf(b2x * b2x + b2y * b2y + b2z * b2z);
                float ux = b2x * inv, uy = b2y * inv, uz = b2z * inv;
                float m1x = n1y * uz - n1z * uy, m1y = n1z * ux - n1x * uz, m1z = n1x * uy - n1y * ux;
                float yv = m1x * n2x + m1y * n2y + m1z * n2z;
                float xv = n1x * n2x + n1y * n2y + n1z * n2z;
                float rn = rsqrtf(xv * xv + yv * yv);
                s_geo[t * 2 + 0] = yv * rn;
                s_geo[t * 2 + 1] = xv * rn;
            }
        } else {
            if (G == 1) s_geo[t] = 0.f;
            else { s_geo[t * 2 + 0] = 0.f; s_geo[t * 2 + 1] = 0.f; }
        }
    }
    __syncthreads();

    // ldmatrix per-thread base byte offset into A
    const uint32_t a_off = (uint32_t)((mw * 32 + (lane & 15)) * ASTRIDE + (lane >> 4) * 8) * 2;
    const uint32_t abase = smb + SM_A + a_off;

    float h[32];   // staged h1 values for one tile (this thread's 32 rows)

    // ---- layer1 compute into registers (LDG-heavy; issued ahead of MMA) ----
    auto layer1_regs = [&](int tile) {
        const int li0 = tile * TILE_M + half * 32;
        int sq[NE];
        #pragma unroll
        for (int k = 0; k < NE; k++) sq[k] = s_seq[li0 + k];
        #pragma unroll
        for (int e = 0; e < 32; e++) {
            const int li = li0 + e;
            float acc = b1j;
            if (G == 2) {
                float2 sc = ((const float2*)s_geo)[li];
                acc = fmaf(sc.x, w1g0, fmaf(sc.y, w1g1, acc));
            } else {
                acc = fmaf(s_geo[li], w1g0, acc);
            }
            #pragma unroll
            for (int k = 0; k < NE; k++)
                acc += __ldg(&Pg[(k * 20 + sq[k]) * HF + jcol]);
            #pragma unroll
            for (int k = 0; k < NE - 1; k++) sq[k] = sq[k + 1];
            sq[NE - 1] = s_seq[li + NE];
            h[e] = fmaxf(acc, 0.f);
        }
    };
    // ---- store staged h1 to A smem (hi/lo split) ----
    auto store_A = [&]() {
        #pragma unroll
        for (int e = 0; e < 32; e++) {
            int row = half * 32 + e;
            __nv_bfloat16 hb = __float2bfloat16(h[e]);
            float lf = h[e] - __bfloat162float(hb);
            s_Ahi[row * ASTRIDE + jcol] = hb;
            s_Alo[row * ASTRIDE + jcol] = __float2bfloat16(lf);
        }
    };

    float thread_sum = 0.f;

    layer1_regs(0);
    store_A();
    __syncthreads();

    for (int tile = 0; tile < NTILES; tile++) {
        // stage next tile's h1 (LDGs overlap the MMA below)
        if (tile + 1 < NTILES) layer1_regs(tile + 1);

        // ---- MMA on A: C = Ahi*Bhi + Ahi*Blo + Alo*Bhi ----
        float c[2][4][4];
        #pragma unroll
        for (int mt = 0; mt < 2; mt++)
            #pragma unroll
            for (int nt = 0; nt < 4; nt++)
                #pragma unroll
                for (int q = 0; q < 4; q++) c[mt][nt][q] = 0.f;

        #pragma unroll
        for (int kt = 0; kt < 8; kt++) {
            uint4 bb[4];
            #pragma unroll
            for (int nt = 0; nt < 4; nt++)
                bb[nt] = s_B4[(kt * 4 + tig) * B4STRIDE + nw * 32 + nt * 8 + gid];
            #pragma unroll
            for (int mt = 0; mt < 2; mt++) {
                uint32_t ah[4], al[4];
                ldmatrix4(ah, abase + (uint32_t)(mt * 16 * ASTRIDE * 2 + kt * 32));
                ldmatrix4(al, abase + (uint32_t)(17408 + mt * 16 * ASTRIDE * 2 + kt * 32));
                #pragma unroll
                for (int nt = 0; nt < 4; nt++) {
                    mma_bf16(c[mt][nt], ah, bb[nt].x, bb[nt].y);
                    mma_bf16(c[mt][nt], ah, bb[nt].z, bb[nt].w);
                    mma_bf16(c[mt][nt], al, bb[nt].x, bb[nt].y);
                }
            }
        }

        // ---- epilogue: sum relu(D + b2)*w3 over valid rows ----
        {
            const int e0 = cstart + tile * TILE_M + mw * 32;
            #pragma unroll
            for (int mt = 0; mt < 2; mt++) {
                const int r0 = mt * 16 + gid;
                const bool v0 = (e0 + r0) < Nelem;
                const bool v1 = (e0 + r0 + 8) < Nelem;
                float p0 = 0.f, p1 = 0.f;
                #pragma unroll
                for (int nt = 0; nt < 4; nt++) {
                    p0 += fmaxf(c[mt][nt][0] + b2v[nt * 2 + 0], 0.f) * w3v[nt * 2 + 0]
                        + fmaxf(c[mt][nt][1] + b2v[nt * 2 + 1], 0.f) * w3v[nt * 2 + 1];
                    p1 += fmaxf(c[mt][nt][2] + b2v[nt * 2 + 0], 0.f) * w3v[nt * 2 + 0]
                        + fmaxf(c[mt][nt][3] + b2v[nt * 2 + 1], 0.f) * w3v[nt * 2 + 1];
                }
                thread_sum += (v0 ? p0 : 0.f) + (v1 ? p1 : 0.f);
            }
        }

        if (tile + 1 < NTILES) {
            __syncthreads();   // all warps done reading A
            store_A();
            __syncthreads();   // A ready for next MMA
        }
    }

    // ---- final reduction ----
    #pragma unroll
    for (int off = 16; off; off >>= 1)
        thread_sum += __shfl_xor_sync(0xffffffffu, thread_sum, off);
    if (lane == 0) s_red[wid] = thread_sum;
    __syncthreads();
    if (tid == 0) {
        int count = Nelem - cstart;
        if (count > CHUNK) count = CHUNK;
        if (count < 0) count = 0;
        float total = 0.f;
        #pragma unroll
        for (int w = 0; w < 8; w++) total += s_red[w];
        atomicAdd(&out[b], total + (float)count * b3s);
    }
}

__global__ __launch_bounds__(THREADS, 2)
void fused_energy_kernel(const float* __restrict__ R, const int* __restrict__ seq,
                         const float* fl_W1, const float* fl_b1, const float* fl_b2,
                         const float* fl_W3, const float* fl_b3,
                         const float* ft_W1, const float* ft_b1, const float* ft_b2,
                         const float* ft_W3, const float* ft_b3,
                         const float* fp_W1, const float* fp_b1, const float* fp_b2,
                         const float* fp_W3, const float* fp_b3,
                         float* __restrict__ out) {
    extern __shared__ char sm[];
    uint32_t smb = smem_u32(sm);
    if (blockIdx.z == 0) {
        run_type<0, 1, 2>(sm, smb, R, seq, g_P + 0 * 20 * HF,
                          fl_W1, fl_b1, fl_b2, fl_W3, fl_b3, g_B4[0], out);
    } else if (blockIdx.z == 1) {
        run_type<1, 1, 3>(sm, smb, R, seq, g_P + 2 * 20 * HF,
                          ft_W1, ft_b1, ft_b2, ft_W3, ft_b3, g_B4[1], out);
    } else {
        run_type<2, 2, 4>(sm, smb, R, seq, g_P + 5 * 20 * HF,
                          fp_W1, fp_b1, fp_b2, fp_W3, fp_b3, g_B4[2], out);
    }
}

extern "C" void kernel_launch(void* const* d_in, const int* in_sizes, int n_in,
                              void* d_out, int out_size) {
    const float* R   = (const float*)d_in[0];
    const int*   seq = (const int*)d_in[1];
    const float* emb = (const float*)d_in[2];
    const float* fl_W1 = (const float*)d_in[3];
    const float* fl_b1 = (const float*)d_in[4];
    const float* fl_W2 = (const float*)d_in[5];
    const float* fl_b2 = (const float*)d_in[6];
    const float* fl_W3 = (const float*)d_in[7];
    const float* fl_b3 = (const float*)d_in[8];
    const float* ft_W1 = (const float*)d_in[9];
    const float* ft_b1 = (const float*)d_in[10];
    const float* ft_W2 = (const float*)d_in[11];
    const float* ft_b2 = (const float*)d_in[12];
    const float* ft_W3 = (const float*)d_in[13];
    const float* ft_b3 = (const float*)d_in[14];
    const float* fp_W1 = (const float*)d_in[15];
    const float* fp_b1 = (const float*)d_in[16];
    const float* fp_W2 = (const float*)d_in[17];
    const float* fp_b2 = (const float*)d_in[18];
    const float* fp_W3 = (const float*)d_in[19];
    const float* fp_b3 = (const float*)d_in[20];
    float* out = (float*)d_out;

    cudaFuncSetAttribute(fused_energy_kernel,
                         cudaFuncAttributeMaxDynamicSharedMemorySize, SM_TOTAL);

    zero_out_kernel<<<1, 128>>>(out);

    dim3 pgrid(20, 9);
    precompute_P_kernel<<<pgrid, 128>>>(emb, fl_W1, ft_W1, fp_W1);
    dim3 bgrid(128, 3);
    precompute_B4_kernel<<<bgrid, 32>>>(fl_W2, ft_W2, fp_W2);

    dim3 grid(3, BATCH, 3);  // 3 chunks x 128 batches x 3 types = 1152 CTAs (~4 waves)
    fused_energy_kernel<<<grid, THREADS, SM_TOTAL>>>(R, seq,
        fl_W1, fl_b1, fl_b2, fl_W3, fl_b3,
        ft_W1, ft_b1, ft_b2, ft_W3, ft_b3,
        fp_W1, fp_b1, fp_b2, fp_W3, fp_b3, out);
}

// round 13
// speedup vs baseline: 1.6231x; 1.0138x over previous
#include <cuda_runtime.h>
#include <cuda_bf16.h>
#include <cstdint>

#define HF 128
#define LSEQ 2048
#define BATCH 128
#define CHUNK 704
#define TILE_M 64
#define NTILES 11
#define THREADS 256

#define ASTRIDE 136    // A row stride in bf16 (272B -> ldmatrix conflict-free)
#define B4STRIDE 130   // B image row stride in uint4 (conflict-free LDS.128)

// smem byte offsets
#define SM_B4    0
#define SM_A     66560            // Ahi 17408 | Alo 17408
#define SM_GEO   101376           // 704*2*4 = 5632
#define SM_SEQ   107008           // 708*4 = 2832
#define SM_RED   109840
#define SM_TOTAL 109904

// ---------------- helpers ----------------
__device__ __forceinline__ uint32_t smem_u32(const void* p) {
    uint32_t a;
    asm("{ .reg .u64 t; cvta.to.shared.u64 t, %1; cvt.u32.u64 %0, t; }" : "=r"(a) : "l"(p));
    return a;
}
__device__ __forceinline__ void ldmatrix4(uint32_t a[4], uint32_t addr) {
    asm volatile("ldmatrix.sync.aligned.m8n8.x4.shared.b16 {%0,%1,%2,%3}, [%4];"
                 : "=r"(a[0]), "=r"(a[1]), "=r"(a[2]), "=r"(a[3]) : "r"(addr));
}
__device__ __forceinline__ void mma_bf16(float c[4], const uint32_t a[4],
                                         uint32_t b0, uint32_t b1) {
    asm volatile("mma.sync.aligned.m16n8k16.row.col.f32.bf16.bf16.f32 "
                 "{%0,%1,%2,%3}, {%4,%5,%6,%7}, {%8,%9}, {%0,%1,%2,%3};"
                 : "+f"(c[0]), "+f"(c[1]), "+f"(c[2]), "+f"(c[3])
                 : "r"(a[0]), "r"(a[1]), "r"(a[2]), "r"(a[3]), "r"(b0), "r"(b1));
}
__device__ __forceinline__ uint32_t pack_bf16(float x, float y) {
    __nv_bfloat16 bx = __float2bfloat16(x), by = __float2bfloat16(y);
    return (uint32_t)__bfloat16_as_ushort(bx) | ((uint32_t)__bfloat16_as_ushort(by) << 16);
}

// ---------------- globals ----------------
__device__ float g_P[9 * 20 * HF];
__device__ uint4 g_B4[3][32 * B4STRIDE];   // interleaved {bh0,bh1,bl0,bl1} frag image

__global__ void zero_out_kernel(float* out) { out[threadIdx.x] = 0.f; }

__global__ void precompute_P_kernel(const float* __restrict__ emb,
                                    const float* __restrict__ W1_0,
                                    const float* __restrict__ W1_1,
                                    const float* __restrict__ W1_2) {
    int aa = blockIdx.x, gk = blockIdx.y, j = threadIdx.x;
    const float* W1; int k, G;
    if (gk < 2)      { W1 = W1_0; k = gk;     G = 1; }
    else if (gk < 5) { W1 = W1_1; k = gk - 2; G = 1; }
    else             { W1 = W1_2; k = gk - 5; G = 2; }
    float s = 0.f;
    #pragma unroll
    for (int c = 0; c < 16; c++)
        s += emb[aa * 16 + c] * W1[(G + k * 16 + c) * HF + j];
    g_P[(gk * 20 + aa) * HF + j] = s;
}

// Per (kt, tig, n): b0 covers k rows {16kt+2tig, +1}, b1 covers {16kt+8+2tig, +1}.
__global__ void precompute_B4_kernel(const float* __restrict__ W2_0,
                                     const float* __restrict__ W2_1,
                                     const float* __restrict__ W2_2) {
    int n = blockIdx.x, type = blockIdx.y, t = threadIdx.x;  // t 0..31
    const float* W2 = (type == 0) ? W2_0 : (type == 1) ? W2_1 : W2_2;
    int kt = t >> 2, tig = t & 3;
    int kA = 16 * kt + 2 * tig;
    int kB = kA + 8;
    float w00 = W2[kA * HF + n],  w01 = W2[(kA + 1) * HF + n];
    float w10 = W2[kB * HF + n],  w11 = W2[(kB + 1) * HF + n];
    __nv_bfloat16 h00 = __float2bfloat16(w00), h01 = __float2bfloat16(w01);
    __nv_bfloat16 h10 = __float2bfloat16(w10), h11 = __float2bfloat16(w11);
    __nv_bfloat16 l00 = __float2bfloat16(w00 - __bfloat162float(h00));
    __nv_bfloat16 l01 = __float2bfloat16(w01 - __bfloat162float(h01));
    __nv_bfloat16 l10 = __float2bfloat16(w10 - __bfloat162float(h10));
    __nv_bfloat16 l11 = __float2bfloat16(w11 - __bfloat162float(h11));
    uint4 v;
    v.x = (uint32_t)__bfloat16_as_ushort(h00) | ((uint32_t)__bfloat16_as_ushort(h01) << 16);
    v.y = (uint32_t)__bfloat16_as_ushort(h10) | ((uint32_t)__bfloat16_as_ushort(h11) << 16);
    v.z = (uint32_t)__bfloat16_as_ushort(l00) | ((uint32_t)__bfloat16_as_ushort(l01) << 16);
    v.w = (uint32_t)__bfloat16_as_ushort(l10) | ((uint32_t)__bfloat16_as_ushort(l11) << 16);
    g_B4[type][t * B4STRIDE + n] = v;
}

// ---------------- main fused kernel ----------------
template <int TYPE, int G, int NE>
__device__ __forceinline__ void run_type(
        char* sm, uint32_t smb,
        const float* __restrict__ R, const int* __restrict__ seq,
        const float* __restrict__ Pg,
        const float* __restrict__ W1, const float* __restrict__ b1,
        const float* __restrict__ b2, const float* __restrict__ W3,
        const float* __restrict__ b3,
        const uint4* __restrict__ B4_g,
        float* __restrict__ out) {
    constexpr int Nelem = LSEQ - 1 - TYPE;

    int*   s_seq = (int*)(sm + SM_SEQ);
    float* s_geo = (float*)(sm + SM_GEO);
    float* s_red = (float*)(sm + SM_RED);
    __nv_bfloat16* s_Ahi = (__nv_bfloat16*)(sm + SM_A);
    __nv_bfloat16* s_Alo = (__nv_bfloat16*)(sm + SM_A + 17408);
    const uint4* s_B4 = (const uint4*)(sm + SM_B4);

    const int tid  = threadIdx.x;
    const int lane = tid & 31;
    const int wid  = tid >> 5;
    const int mw   = wid >> 2;       // 0..1 : M-half (32 rows each)
    const int nw   = wid & 3;        // 0..3 : N-quarter
    const int gid  = lane >> 2;      // 0..7
    const int tig  = lane & 3;       // 0..3
    const int jp   = tid & 63;       // layer1: column pair {2jp, 2jp+1}
    const int rg   = tid >> 6;       // layer1: row group (16 rows)
    const int b    = blockIdx.y;
    const int cstart = blockIdx.x * CHUNK;

    // ---- B image -> smem ----
    {
        uint4* db = (uint4*)(sm + SM_B4);
        for (int t = tid; t < 32 * B4STRIDE; t += THREADS) db[t] = B4_g[t];
    }
    for (int t = tid; t < CHUNK + 4; t += THREADS) {
        int idx = cstart + t;
        if (idx >= LSEQ) idx = LSEQ - 1;
        s_seq[t] = seq[b * LSEQ + idx];
    }
    const float b1j0 = b1[2 * jp],      b1j1 = b1[2 * jp + 1];
    const float w1a0 = W1[2 * jp],      w1a1 = W1[2 * jp + 1];
    const float w1b0 = (G == 2) ? W1[HF + 2 * jp]     : 0.f;
    const float w1b1 = (G == 2) ? W1[HF + 2 * jp + 1] : 0.f;
    const float b3s  = b3[0];

    // per-thread epilogue coefficients for its 8 columns
    float b2v[8], w3v[8];
    #pragma unroll
    for (int nt = 0; nt < 4; nt++) {
        #pragma unroll
        for (int u = 0; u < 2; u++) {
            int c = nw * 32 + nt * 8 + tig * 2 + u;
            b2v[nt * 2 + u] = __ldg(&b2[c]);
            w3v[nt * 2 + u] = __ldg(&W3[c]);
        }
    }

    // ---- geometry for the whole chunk ----
    const float* Rb = R + (size_t)b * LSEQ * 3;
    for (int t = tid; t < CHUNK; t += THREADS) {
        int i = cstart + t;
        if (i < Nelem) {
            if (TYPE == 0) {
                float dx = __ldg(&Rb[(i + 1) * 3 + 0]) - __ldg(&Rb[i * 3 + 0]);
                float dy = __ldg(&Rb[(i + 1) * 3 + 1]) - __ldg(&Rb[i * 3 + 1]);
                float dz = __ldg(&Rb[(i + 1) * 3 + 2]) - __ldg(&Rb[i * 3 + 2]);
                s_geo[t] = sqrtf(dx * dx + dy * dy + dz * dz);
            } else if (TYPE == 1) {
                float ax = __ldg(&Rb[i * 3 + 0]), ay = __ldg(&Rb[i * 3 + 1]), az = __ldg(&Rb[i * 3 + 2]);
                float bx = __ldg(&Rb[(i + 1) * 3 + 0]), by = __ldg(&Rb[(i + 1) * 3 + 1]), bz = __ldg(&Rb[(i + 1) * 3 + 2]);
                float cx = __ldg(&Rb[(i + 2) * 3 + 0]), cy = __ldg(&Rb[(i + 2) * 3 + 1]), cz = __ldg(&Rb[(i + 2) * 3 + 2]);
                float ux = ax - bx, uy = ay - by, uz = az - bz;
                float vx = cx - bx, vy = cy - by, vz = cz - bz;
                float num = ux * vx + uy * vy + uz * vz;
                float den = sqrtf((ux * ux + uy * uy + uz * uz) * (vx * vx + vy * vy + vz * vz));
                float c = num / den;
                s_geo[t] = fminf(1.f, fmaxf(-1.f, c));
            } else {
                float p0x = __ldg(&Rb[i * 3 + 0]), p0y = __ldg(&Rb[i * 3 + 1]), p0z = __ldg(&Rb[i * 3 + 2]);
                float p1x = __ldg(&Rb[(i + 1) * 3 + 0]), p1y = __ldg(&Rb[(i + 1) * 3 + 1]), p1z = __ldg(&Rb[(i + 1) * 3 + 2]);
                float p2x = __ldg(&Rb[(i + 2) * 3 + 0]), p2y = __ldg(&Rb[(i + 2) * 3 + 1]), p2z = __ldg(&Rb[(i + 2) * 3 + 2]);
                float p3x = __ldg(&Rb[(i + 3) * 3 + 0]), p3y = __ldg(&Rb[(i + 3) * 3 + 1]), p3z = __ldg(&Rb[(i + 3) * 3 + 2]);
                float b1x = p1x - p0x, b1y = p1y - p0y, b1z = p1z - p0z;
                float b2x = p2x - p1x, b2y = p2y - p1y, b2z = p2z - p1z;
                float b3x = p3x - p2x, b3y = p3y - p2y, b3z = p3z - p2z;
                float n1x = b1y * b2z - b1z * b2y, n1y = b1z * b2x - b1x * b2z, n1z = b1x * b2y - b1y * b2x;
                float n2x = b2y * b3z - b2z * b3y, n2y = b2z * b3x - b2x * b3z, n2z = b2x * b3y - b2y * b3x;
                float inv = rsqrtf(b2x * b2x + b2y * b2y + b2z * b2z);
                float ux = b2x * inv, uy = b2y * inv, uz = b2z * inv;
                float m1x = n1y * uz - n1z * uy, m1y = n1z * ux - n1x * uz, m1z = n1x * uy - n1y * ux;
                float yv = m1x * n2x + m1y * n2y + m1z * n2z;
                float xv = n1x * n2x + n1y * n2y + n1z * n2z;
                float rn = rsqrtf(xv * xv + yv * yv);
                s_geo[t * 2 + 0] = yv * rn;
                s_geo[t * 2 + 1] = xv * rn;
            }
        } else {
            if (G == 1) s_geo[t] = 0.f;
            else { s_geo[t * 2 + 0] = 0.f; s_geo[t * 2 + 1] = 0.f; }
        }
    }
    __syncthreads();

    // ldmatrix per-thread base byte offset into A
    const uint32_t a_off = (uint32_t)((mw * 32 + (lane & 15)) * ASTRIDE + (lane >> 4) * 8) * 2;
    const uint32_t abase = smb + SM_A + a_off;

    float h0[16], h1[16];   // staged h1 for 16 rows x column pair

    // ---- layer1 compute into registers (LDG.64 pairs; overlaps MMA) ----
    auto layer1_regs = [&](int tile) {
        const int li0 = tile * TILE_M + rg * 16;
        #pragma unroll
        for (int e = 0; e < 16; e++) {
            const int li = li0 + e;
            float a0 = b1j0, a1 = b1j1;
            if (G == 2) {
                float2 sc = ((const float2*)s_geo)[li];
                a0 = fmaf(sc.x, w1a0, fmaf(sc.y, w1b0, a0));
                a1 = fmaf(sc.x, w1a1, fmaf(sc.y, w1b1, a1));
            } else {
                float g = s_geo[li];
                a0 = fmaf(g, w1a0, a0);
                a1 = fmaf(g, w1a1, a1);
            }
            #pragma unroll
            for (int k = 0; k < NE; k++) {
                float2 p = __ldg((const float2*)&Pg[(k * 20 + s_seq[li + k]) * HF + 2 * jp]);
                a0 += p.x;
                a1 += p.y;
            }
            h0[e] = fmaxf(a0, 0.f);
            h1[e] = fmaxf(a1, 0.f);
        }
    };
    // ---- store staged h1 to A smem (packed hi/lo STS.32) ----
    auto store_A = [&]() {
        #pragma unroll
        for (int e = 0; e < 16; e++) {
            int row = rg * 16 + e;
            __nv_bfloat16 hb0 = __float2bfloat16(h0[e]);
            __nv_bfloat16 hb1 = __float2bfloat16(h1[e]);
            uint32_t hipk = (uint32_t)__bfloat16_as_ushort(hb0) |
                            ((uint32_t)__bfloat16_as_ushort(hb1) << 16);
            uint32_t lopk = pack_bf16(h0[e] - __bfloat162float(hb0),
                                      h1[e] - __bfloat162float(hb1));
            *(uint32_t*)&s_Ahi[row * ASTRIDE + 2 * jp] = hipk;
            *(uint32_t*)&s_Alo[row * ASTRIDE + 2 * jp] = lopk;
        }
    };

    float thread_sum = 0.f;

    layer1_regs(0);
    store_A();
    __syncthreads();

    for (int tile = 0; tile < NTILES; tile++) {
        // stage next tile's h1 (LDGs overlap the MMA below)
        if (tile + 1 < NTILES) layer1_regs(tile + 1);

        // ---- MMA on A: C = Ahi*Bhi + Ahi*Blo + Alo*Bhi, pass-major order ----
        float c[2][4][4];
        #pragma unroll
        for (int mt = 0; mt < 2; mt++)
            #pragma unroll
            for (int nt = 0; nt < 4; nt++)
                #pragma unroll
                for (int q = 0; q < 4; q++) c[mt][nt][q] = 0.f;

        #pragma unroll
        for (int kt = 0; kt < 8; kt++) {
            uint4 bb[4];
            #pragma unroll
            for (int nt = 0; nt < 4; nt++)
                bb[nt] = s_B4[(kt * 4 + tig) * B4STRIDE + nw * 32 + nt * 8 + gid];
            uint32_t ah[2][4], al[2][4];
            #pragma unroll
            for (int mt = 0; mt < 2; mt++) {
                ldmatrix4(ah[mt], abase + (uint32_t)(mt * 16 * ASTRIDE * 2 + kt * 32));
                ldmatrix4(al[mt], abase + (uint32_t)(17408 + mt * 16 * ASTRIDE * 2 + kt * 32));
            }
            // pass 1: Ahi * Bhi   (8 independent accumulator chains)
            #pragma unroll
            for (int mt = 0; mt < 2; mt++)
                #pragma unroll
                for (int nt = 0; nt < 4; nt++)
                    mma_bf16(c[mt][nt], ah[mt], bb[nt].x, bb[nt].y);
            // pass 2: Ahi * Blo
            #pragma unroll
            for (int mt = 0; mt < 2; mt++)
                #pragma unroll
                for (int nt = 0; nt < 4; nt++)
                    mma_bf16(c[mt][nt], ah[mt], bb[nt].z, bb[nt].w);
            // pass 3: Alo * Bhi
            #pragma unroll
            for (int mt = 0; mt < 2; mt++)
                #pragma unroll
                for (int nt = 0; nt < 4; nt++)
                    mma_bf16(c[mt][nt], al[mt], bb[nt].x, bb[nt].y);
        }

        // ---- epilogue: sum relu(D + b2)*w3 over valid rows ----
        {
            const int e0 = cstart + tile * TILE_M + mw * 32;
            #pragma unroll
            for (int mt = 0; mt < 2; mt++) {
                const int r0 = mt * 16 + gid;
                const bool v0 = (e0 + r0) < Nelem;
                const bool v1 = (e0 + r0 + 8) < Nelem;
                float p0 = 0.f, p1 = 0.f;
                #pragma unroll
                for (int nt = 0; nt < 4; nt++) {
                    p0 += fmaxf(c[mt][nt][0] + b2v[nt * 2 + 0], 0.f) * w3v[nt * 2 + 0]
                        + fmaxf(c[mt][nt][1] + b2v[nt * 2 + 1], 0.f) * w3v[nt * 2 + 1];
                    p1 += fmaxf(c[mt][nt][2] + b2v[nt * 2 + 0], 0.f) * w3v[nt * 2 + 0]
                        + fmaxf(c[mt][nt][3] + b2v[nt * 2 + 1], 0.f) * w3v[nt * 2 + 1];
                }
                thread_sum += (v0 ? p0 : 0.f) + (v1 ? p1 : 0.f);
            }
        }

        if (tile + 1 < NTILES) {
            __syncthreads();   // all warps done reading A
            store_A();
            __syncthreads();   // A ready for next MMA
        }
    }

    // ---- final reduction ----
    #pragma unroll
    for (int off = 16; off; off >>= 1)
        thread_sum += __shfl_xor_sync(0xffffffffu, thread_sum, off);
    if (lane == 0) s_red[wid] = thread_sum;
    __syncthreads();
    if (tid == 0) {
        int count = Nelem - cstart;
        if (count > CHUNK) count = CHUNK;
        if (count < 0) count = 0;
        float total = 0.f;
        #pragma unroll
        for (int w = 0; w < 8; w++) total += s_red[w];
        atomicAdd(&out[b], total + (float)count * b3s);
    }
}

__global__ __launch_bounds__(THREADS, 2)
void fused_energy_kernel(const float* __restrict__ R, const int* __restrict__ seq,
                         const float* fl_W1, const float* fl_b1, const float* fl_b2,
                         const float* fl_W3, const float* fl_b3,
                         const float* ft_W1, const float* ft_b1, const float* ft_b2,
                         const float* ft_W3, const float* ft_b3,
                         const float* fp_W1, const float* fp_b1, const float* fp_b2,
                         const float* fp_W3, const float* fp_b3,
                         float* __restrict__ out) {
    extern __shared__ char sm[];
    uint32_t smb = smem_u32(sm);
    if (blockIdx.z == 0) {
        run_type<0, 1, 2>(sm, smb, R, seq, g_P + 0 * 20 * HF,
                          fl_W1, fl_b1, fl_b2, fl_W3, fl_b3, g_B4[0], out);
    } else if (blockIdx.z == 1) {
        run_type<1, 1, 3>(sm, smb, R, seq, g_P + 2 * 20 * HF,
                          ft_W1, ft_b1, ft_b2, ft_W3, ft_b3, g_B4[1], out);
    } else {
        run_type<2, 2, 4>(sm, smb, R, seq, g_P + 5 * 20 * HF,
                          fp_W1, fp_b1, fp_b2, fp_W3, fp_b3, g_B4[2], out);
    }
}

extern "C" void kernel_launch(void* const* d_in, const int* in_sizes, int n_in,
                              void* d_out, int out_size) {
    const float* R   = (const float*)d_in[0];
    const int*   seq = (const int*)d_in[1];
    const float* emb = (const float*)d_in[2];
    const float* fl_W1 = (const float*)d_in[3];
    const float* fl_b1 = (const float*)d_in[4];
    const float* fl_W2 = (const float*)d_in[5];
    const float* fl_b2 = (const float*)d_in[6];
    const float* fl_W3 = (const float*)d_in[7];
    const float* fl_b3 = (const float*)d_in[8];
    const float* ft_W1 = (const float*)d_in[9];
    const float* ft_b1 = (const float*)d_in[10];
    const float* ft_W2 = (const float*)d_in[11];
    const float* ft_b2 = (const float*)d_in[12];
    const float* ft_W3 = (const float*)d_in[13];
    const float* ft_b3 = (const float*)d_in[14];
    const float* fp_W1 = (const float*)d_in[15];
    const float* fp_b1 = (const float*)d_in[16];
    const float* fp_W2 = (const float*)d_in[17];
    const float* fp_b2 = (const float*)d_in[18];
    const float* fp_W3 = (const float*)d_in[19];
    const float* fp_b3 = (const float*)d_in[20];
    float* out = (float*)d_out;

    cudaFuncSetAttribute(fused_energy_kernel,
                         cudaFuncAttributeMaxDynamicSharedMemorySize, SM_TOTAL);

    zero_out_kernel<<<1, 128>>>(out);

    dim3 pgrid(20, 9);
    precompute_P_kernel<<<pgrid, 128>>>(emb, fl_W1, ft_W1, fp_W1);
    dim3 bgrid(128, 3);
    precompute_B4_kernel<<<bgrid, 32>>>(fl_W2, ft_W2, fp_W2);

    dim3 grid(3, BATCH, 3);  // 1152 CTAs (~4 waves at 2 CTA/SM)
    fused_energy_kernel<<<grid, THREADS, SM_TOTAL>>>(R, seq,
        fl_W1, fl_b1, fl_b2, fl_W3, fl_b3,
        ft_W1, ft_b1, ft_b2, ft_W3, ft_b3,
        fp_W1, fp_b1, fp_b2, fp_W3, fp_b3, out);
}

// round 14
// speedup vs baseline: 2.1019x; 1.2950x over previous
#include <cuda_runtime.h>
#include <cuda_bf16.h>
#include <cstdint>

#define HF 128
#define LSEQ 2048
#define BATCH 128
#define CHUNK 704
#define TILE_M 64
#define NTILES 11
#define THREADS 256

#define ASTRIDE 136    // A row stride in bf16 (272B -> ldmatrix conflict-free)
#define B4STRIDE 130   // B image row stride in uint4 (conflict-free LDS.128)

// smem byte offsets
#define SM_B4    0                 // 66560
#define SM_A     66560             // Ahi only: 17408
#define SM_GEO   83968             // 704*2*4 = 5632
#define SM_SEQ   89600             // 708*4 = 2832
#define SM_RED   92432
#define SM_TOTAL 92496

// ---------------- helpers ----------------
__device__ __forceinline__ uint32_t smem_u32(const void* p) {
    uint32_t a;
    asm("{ .reg .u64 t; cvta.to.shared.u64 t, %1; cvt.u32.u64 %0, t; }" : "=r"(a) : "l"(p));
    return a;
}
__device__ __forceinline__ void ldmatrix4(uint32_t a[4], uint32_t addr) {
    asm volatile("ldmatrix.sync.aligned.m8n8.x4.shared.b16 {%0,%1,%2,%3}, [%4];"
                 : "=r"(a[0]), "=r"(a[1]), "=r"(a[2]), "=r"(a[3]) : "r"(addr));
}
__device__ __forceinline__ void mma_bf16(float c[4], const uint32_t a[4],
                                         uint32_t b0, uint32_t b1) {
    asm volatile("mma.sync.aligned.m16n8k16.row.col.f32.bf16.bf16.f32 "
                 "{%0,%1,%2,%3}, {%4,%5,%6,%7}, {%8,%9}, {%0,%1,%2,%3};"
                 : "+f"(c[0]), "+f"(c[1]), "+f"(c[2]), "+f"(c[3])
                 : "r"(a[0]), "r"(a[1]), "r"(a[2]), "r"(a[3]), "r"(b0), "r"(b1));
}
__device__ __forceinline__ uint32_t pack_bf16(float x, float y) {
    __nv_bfloat16 bx = __float2bfloat16(x), by = __float2bfloat16(y);
    return (uint32_t)__bfloat16_as_ushort(bx) | ((uint32_t)__bfloat16_as_ushort(by) << 16);
}

// ---------------- globals ----------------
__device__ float g_P[9 * 20 * HF];
__device__ uint4 g_B4[3][32 * B4STRIDE];   // interleaved {bh0,bh1,bl0,bl1} frag image

__global__ void zero_out_kernel(float* out) { out[threadIdx.x] = 0.f; }

__global__ void precompute_P_kernel(const float* __restrict__ emb,
                                    const float* __restrict__ W1_0,
                                    const float* __restrict__ W1_1,
                                    const float* __restrict__ W1_2) {
    int aa = blockIdx.x, gk = blockIdx.y, j = threadIdx.x;
    const float* W1; int k, G;
    if (gk < 2)      { W1 = W1_0; k = gk;     G = 1; }
    else if (gk < 5) { W1 = W1_1; k = gk - 2; G = 1; }
    else             { W1 = W1_2; k = gk - 5; G = 2; }
    float s = 0.f;
    #pragma unroll
    for (int c = 0; c < 16; c++)
        s += emb[aa * 16 + c] * W1[(G + k * 16 + c) * HF + j];
    g_P[(gk * 20 + aa) * HF + j] = s;
}

// Per (kt, tig, n): b0 covers k rows {16kt+2tig, +1}, b1 covers {16kt+8+2tig, +1}.
__global__ void precompute_B4_kernel(const float* __restrict__ W2_0,
                                     const float* __restrict__ W2_1,
                                     const float* __restrict__ W2_2) {
    int n = blockIdx.x, type = blockIdx.y, t = threadIdx.x;  // t 0..31
    const float* W2 = (type == 0) ? W2_0 : (type == 1) ? W2_1 : W2_2;
    int kt = t >> 2, tig = t & 3;
    int kA = 16 * kt + 2 * tig;
    int kB = kA + 8;
    float w00 = W2[kA * HF + n],  w01 = W2[(kA + 1) * HF + n];
    float w10 = W2[kB * HF + n],  w11 = W2[(kB + 1) * HF + n];
    __nv_bfloat16 h00 = __float2bfloat16(w00), h01 = __float2bfloat16(w01);
    __nv_bfloat16 h10 = __float2bfloat16(w10), h11 = __float2bfloat16(w11);
    __nv_bfloat16 l00 = __float2bfloat16(w00 - __bfloat162float(h00));
    __nv_bfloat16 l01 = __float2bfloat16(w01 - __bfloat162float(h01));
    __nv_bfloat16 l10 = __float2bfloat16(w10 - __bfloat162float(h10));
    __nv_bfloat16 l11 = __float2bfloat16(w11 - __bfloat162float(h11));
    uint4 v;
    v.x = (uint32_t)__bfloat16_as_ushort(h00) | ((uint32_t)__bfloat16_as_ushort(h01) << 16);
    v.y = (uint32_t)__bfloat16_as_ushort(h10) | ((uint32_t)__bfloat16_as_ushort(h11) << 16);
    v.z = (uint32_t)__bfloat16_as_ushort(l00) | ((uint32_t)__bfloat16_as_ushort(l01) << 16);
    v.w = (uint32_t)__bfloat16_as_ushort(l10) | ((uint32_t)__bfloat16_as_ushort(l11) << 16);
    g_B4[type][t * B4STRIDE + n] = v;
}

// ---------------- main fused kernel ----------------
template <int TYPE, int G, int NE>
__device__ __forceinline__ void run_type(
        char* sm, uint32_t smb,
        const float* __restrict__ R, const int* __restrict__ seq,
        const float* __restrict__ Pg,
        const float* __restrict__ W1, const float* __restrict__ b1,
        const float* __restrict__ b2, const float* __restrict__ W3,
        const float* __restrict__ b3,
        const uint4* __restrict__ B4_g,
        float* __restrict__ out) {
    constexpr int Nelem = LSEQ - 1 - TYPE;

    int*   s_seq = (int*)(sm + SM_SEQ);
    float* s_geo = (float*)(sm + SM_GEO);
    float* s_red = (float*)(sm + SM_RED);
    __nv_bfloat16* s_Ahi = (__nv_bfloat16*)(sm + SM_A);
    const uint4* s_B4 = (const uint4*)(sm + SM_B4);

    const int tid  = threadIdx.x;
    const int lane = tid & 31;
    const int wid  = tid >> 5;
    const int mw   = wid >> 2;       // 0..1 : M-half (32 rows each)
    const int nw   = wid & 3;        // 0..3 : N-quarter
    const int gid  = lane >> 2;      // 0..7
    const int tig  = lane & 3;       // 0..3
    const int jp   = tid & 63;       // layer1: column pair {2jp, 2jp+1}
    const int rg   = tid >> 6;       // layer1: row group (16 rows)
    const int b    = blockIdx.y;
    const int cstart = blockIdx.x * CHUNK;

    // ---- B image -> smem ----
    {
        uint4* db = (uint4*)(sm + SM_B4);
        for (int t = tid; t < 32 * B4STRIDE; t += THREADS) db[t] = B4_g[t];
    }
    for (int t = tid; t < CHUNK + 4; t += THREADS) {
        int idx = cstart + t;
        if (idx >= LSEQ) idx = LSEQ - 1;
        s_seq[t] = seq[b * LSEQ + idx];
    }
    const float b1j0 = b1[2 * jp],      b1j1 = b1[2 * jp + 1];
    const float w1a0 = W1[2 * jp],      w1a1 = W1[2 * jp + 1];
    const float w1b0 = (G == 2) ? W1[HF + 2 * jp]     : 0.f;
    const float w1b1 = (G == 2) ? W1[HF + 2 * jp + 1] : 0.f;
    const float b3s  = b3[0];

    // per-thread epilogue coefficients for its 8 columns
    float b2v[8], w3v[8];
    #pragma unroll
    for (int nt = 0; nt < 4; nt++) {
        #pragma unroll
        for (int u = 0; u < 2; u++) {
            int c = nw * 32 + nt * 8 + tig * 2 + u;
            b2v[nt * 2 + u] = __ldg(&b2[c]);
            w3v[nt * 2 + u] = __ldg(&W3[c]);
        }
    }

    // ---- geometry for the whole chunk ----
    const float* Rb = R + (size_t)b * LSEQ * 3;
    for (int t = tid; t < CHUNK; t += THREADS) {
        int i = cstart + t;
        if (i < Nelem) {
            if (TYPE == 0) {
                float dx = __ldg(&Rb[(i + 1) * 3 + 0]) - __ldg(&Rb[i * 3 + 0]);
                float dy = __ldg(&Rb[(i + 1) * 3 + 1]) - __ldg(&Rb[i * 3 + 1]);
                float dz = __ldg(&Rb[(i + 1) * 3 + 2]) - __ldg(&Rb[i * 3 + 2]);
                s_geo[t] = sqrtf(dx * dx + dy * dy + dz * dz);
            } else if (TYPE == 1) {
                float ax = __ldg(&Rb[i * 3 + 0]), ay = __ldg(&Rb[i * 3 + 1]), az = __ldg(&Rb[i * 3 + 2]);
                float bx = __ldg(&Rb[(i + 1) * 3 + 0]), by = __ldg(&Rb[(i + 1) * 3 + 1]), bz = __ldg(&Rb[(i + 1) * 3 + 2]);
                float cx = __ldg(&Rb[(i + 2) * 3 + 0]), cy = __ldg(&Rb[(i + 2) * 3 + 1]), cz = __ldg(&Rb[(i + 2) * 3 + 2]);
                float ux = ax - bx, uy = ay - by, uz = az - bz;
                float vx = cx - bx, vy = cy - by, vz = cz - bz;
                float num = ux * vx + uy * vy + uz * vz;
                float den = sqrtf((ux * ux + uy * uy + uz * uz) * (vx * vx + vy * vy + vz * vz));
                float c = num / den;
                s_geo[t] = fminf(1.f, fmaxf(-1.f, c));
            } else {
                float p0x = __ldg(&Rb[i * 3 + 0]), p0y = __ldg(&Rb[i * 3 + 1]), p0z = __ldg(&Rb[i * 3 + 2]);
                float p1x = __ldg(&Rb[(i + 1) * 3 + 0]), p1y = __ldg(&Rb[(i + 1) * 3 + 1]), p1z = __ldg(&Rb[(i + 1) * 3 + 2]);
                float p2x = __ldg(&Rb[(i + 2) * 3 + 0]), p2y = __ldg(&Rb[(i + 2) * 3 + 1]), p2z = __ldg(&Rb[(i + 2) * 3 + 2]);
                float p3x = __ldg(&Rb[(i + 3) * 3 + 0]), p3y = __ldg(&Rb[(i + 3) * 3 + 1]), p3z = __ldg(&Rb[(i + 3) * 3 + 2]);
                float b1x = p1x - p0x, b1y = p1y - p0y, b1z = p1z - p0z;
                float b2x = p2x - p1x, b2y = p2y - p1y, b2z = p2z - p1z;
                float b3x = p3x - p2x, b3y = p3y - p2y, b3z = p3z - p2z;
                float n1x = b1y * b2z - b1z * b2y, n1y = b1z * b2x - b1x * b2z, n1z = b1x * b2y - b1y * b2x;
                float n2x = b2y * b3z - b2z * b3y, n2y = b2z * b3x - b2x * b3z, n2z = b2x * b3y - b2y * b3x;
                float inv = rsqrtf(b2x * b2x + b2y * b2y + b2z * b2z);
                float ux = b2x * inv, uy = b2y * inv, uz = b2z * inv;
                float m1x = n1y * uz - n1z * uy, m1y = n1z * ux - n1x * uz, m1z = n1x * uy - n1y * ux;
                float yv = m1x * n2x + m1y * n2y + m1z * n2z;
                float xv = n1x * n2x + n1y * n2y + n1z * n2z;
                float rn = rsqrtf(xv * xv + yv * yv);
                s_geo[t * 2 + 0] = yv * rn;
                s_geo[t * 2 + 1] = xv * rn;
            }
        } else {
            if (G == 1) s_geo[t] = 0.f;
            else { s_geo[t * 2 + 0] = 0.f; s_geo[t * 2 + 1] = 0.f; }
        }
    }
    __syncthreads();

    // ldmatrix per-thread base byte offset into A
    const uint32_t a_off = (uint32_t)((mw * 32 + (lane & 15)) * ASTRIDE + (lane >> 4) * 8) * 2;
    const uint32_t abase = smb + SM_A + a_off;

    uint32_t hpk[16];   // staged packed-bf16 h1 pairs for 16 rows

    // ---- layer1 compute into registers (LDG.64 pairs; overlaps MMA) ----
    auto layer1_regs = [&](int tile) {
        const int li0 = tile * TILE_M + rg * 16;
        float a0[16], a1[16];
        #pragma unroll
        for (int e = 0; e < 16; e++) {
            const int li = li0 + e;
            a0[e] = b1j0; a1[e] = b1j1;
            if (G == 2) {
                float2 sc = ((const float2*)s_geo)[li];
                a0[e] = fmaf(sc.x, w1a0, fmaf(sc.y, w1b0, a0[e]));
                a1[e] = fmaf(sc.x, w1a1, fmaf(sc.y, w1b1, a1[e]));
            } else {
                float g = s_geo[li];
                a0[e] = fmaf(g, w1a0, a0[e]);
                a1[e] = fmaf(g, w1a1, a1[e]);
            }
        }
        // k-major: batch 16 independent LDG.64 per k-step, then consume
        #pragma unroll
        for (int k = 0; k < NE; k++) {
            float2 p[16];
            #pragma unroll
            for (int e = 0; e < 16; e++)
                p[e] = __ldg((const float2*)&Pg[(k * 20 + s_seq[li0 + e + k]) * HF + 2 * jp]);
            #pragma unroll
            for (int e = 0; e < 16; e++) { a0[e] += p[e].x; a1[e] += p[e].y; }
        }
        #pragma unroll
        for (int e = 0; e < 16; e++)
            hpk[e] = pack_bf16(fmaxf(a0[e], 0.f), fmaxf(a1[e], 0.f));
    };
    // ---- store staged h1 to A smem ----
    auto store_A = [&]() {
        #pragma unroll
        for (int e = 0; e < 16; e++) {
            int row = rg * 16 + e;
            *(uint32_t*)&s_Ahi[row * ASTRIDE + 2 * jp] = hpk[e];
        }
    };

    float thread_sum = 0.f;

    layer1_regs(0);
    store_A();
    __syncthreads();

    for (int tile = 0; tile < NTILES; tile++) {
        // stage next tile's h1 (LDGs overlap the MMA below)
        if (tile + 1 < NTILES) layer1_regs(tile + 1);

        // ---- MMA on A: C = Ahi*Bhi + Ahi*Blo (2 passes) ----
        float c[2][4][4];
        #pragma unroll
        for (int mt = 0; mt < 2; mt++)
            #pragma unroll
            for (int nt = 0; nt < 4; nt++)
                #pragma unroll
                for (int q = 0; q < 4; q++) c[mt][nt][q] = 0.f;

        #pragma unroll
        for (int kt = 0; kt < 8; kt++) {
            uint4 bb[4];
            #pragma unroll
            for (int nt = 0; nt < 4; nt++)
                bb[nt] = s_B4[(kt * 4 + tig) * B4STRIDE + nw * 32 + nt * 8 + gid];
            uint32_t ah[2][4];
            #pragma unroll
            for (int mt = 0; mt < 2; mt++)
                ldmatrix4(ah[mt], abase + (uint32_t)(mt * 16 * ASTRIDE * 2 + kt * 32));
            // pass 1: Ahi * Bhi
            #pragma unroll
            for (int mt = 0; mt < 2; mt++)
                #pragma unroll
                for (int nt = 0; nt < 4; nt++)
                    mma_bf16(c[mt][nt], ah[mt], bb[nt].x, bb[nt].y);
            // pass 2: Ahi * Blo
            #pragma unroll
            for (int mt = 0; mt < 2; mt++)
                #pragma unroll
                for (int nt = 0; nt < 4; nt++)
                    mma_bf16(c[mt][nt], ah[mt], bb[nt].z, bb[nt].w);
        }

        // ---- epilogue: sum relu(D + b2)*w3 over valid rows ----
        {
            const int e0 = cstart + tile * TILE_M + mw * 32;
            #pragma unroll
            for (int mt = 0; mt < 2; mt++) {
                const int r0 = mt * 16 + gid;
                const bool v0 = (e0 + r0) < Nelem;
                const bool v1 = (e0 + r0 + 8) < Nelem;
                float p0 = 0.f, p1 = 0.f;
                #pragma unroll
                for (int nt = 0; nt < 4; nt++) {
                    p0 += fmaxf(c[mt][nt][0] + b2v[nt * 2 + 0], 0.f) * w3v[nt * 2 + 0]
                        + fmaxf(c[mt][nt][1] + b2v[nt * 2 + 1], 0.f) * w3v[nt * 2 + 1];
                    p1 += fmaxf(c[mt][nt][2] + b2v[nt * 2 + 0], 0.f) * w3v[nt * 2 + 0]
                        + fmaxf(c[mt][nt][3] + b2v[nt * 2 + 1], 0.f) * w3v[nt * 2 + 1];
                }
                thread_sum += (v0 ? p0 : 0.f) + (v1 ? p1 : 0.f);
            }
        }

        if (tile + 1 < NTILES) {
            __syncthreads();   // all warps done reading A
            store_A();
            __syncthreads();   // A ready for next MMA
        }
    }

    // ---- final reduction ----
    #pragma unroll
    for (int off = 16; off; off >>= 1)
        thread_sum += __shfl_xor_sync(0xffffffffu, thread_sum, off);
    if (lane == 0) s_red[wid] = thread_sum;
    __syncthreads();
    if (tid == 0) {
        int count = Nelem - cstart;
        if (count > CHUNK) count = CHUNK;
        if (count < 0) count = 0;
        float total = 0.f;
        #pragma unroll
        for (int w = 0; w < 8; w++) total += s_red[w];
        atomicAdd(&out[b], total + (float)count * b3s);
    }
}

__global__ __launch_bounds__(THREADS, 2)
void fused_energy_kernel(const float* __restrict__ R, const int* __restrict__ seq,
                         const float* fl_W1, const float* fl_b1, const float* fl_b2,
                         const float* fl_W3, const float* fl_b3,
                         const float* ft_W1, const float* ft_b1, const float* ft_b2,
                         const float* ft_W3, const float* ft_b3,
                         const float* fp_W1, const float* fp_b1, const float* fp_b2,
                         const float* fp_W3, const float* fp_b3,
                         float* __restrict__ out) {
    extern __shared__ char sm[];
    uint32_t smb = smem_u32(sm);
    if (blockIdx.z == 0) {
        run_type<0, 1, 2>(sm, smb, R, seq, g_P + 0 * 20 * HF,
                          fl_W1, fl_b1, fl_b2, fl_W3, fl_b3, g_B4[0], out);
    } else if (blockIdx.z == 1) {
        run_type<1, 1, 3>(sm, smb, R, seq, g_P + 2 * 20 * HF,
                          ft_W1, ft_b1, ft_b2, ft_W3, ft_b3, g_B4[1], out);
    } else {
        run_type<2, 2, 4>(sm, smb, R, seq, g_P + 5 * 20 * HF,
                          fp_W1, fp_b1, fp_b2, fp_W3, fp_b3, g_B4[2], out);
    }
}

extern "C" void kernel_launch(void* const* d_in, const int* in_sizes, int n_in,
                              void* d_out, int out_size) {
    const float* R   = (const float*)d_in[0];
    const int*   seq = (const int*)d_in[1];
    const float* emb = (const float*)d_in[2];
    const float* fl_W1 = (const float*)d_in[3];
    const float* fl_b1 = (const float*)d_in[4];
    const float* fl_W2 = (const float*)d_in[5];
    const float* fl_b2 = (const float*)d_in[6];
    const float* fl_W3 = (const float*)d_in[7];
    const float* fl_b3 = (const float*)d_in[8];
    const float* ft_W1 = (const float*)d_in[9];
    const float* ft_b1 = (const float*)d_in[10];
    const float* ft_W2 = (const float*)d_in[11];
    const float* ft_b2 = (const float*)d_in[12];
    const float* ft_W3 = (const float*)d_in[13];
    const float* ft_b3 = (const float*)d_in[14];
    const float* fp_W1 = (const float*)d_in[15];
    const float* fp_b1 = (const float*)d_in[16];
    const float* fp_W2 = (const float*)d_in[17];
    const float* fp_b2 = (const float*)d_in[18];
    const float* fp_W3 = (const float*)d_in[19];
    const float* fp_b3 = (const float*)d_in[20];
    float* out = (float*)d_out;

    cudaFuncSetAttribute(fused_energy_kernel,
                         cudaFuncAttributeMaxDynamicSharedMemorySize, SM_TOTAL);

    zero_out_kernel<<<1, 128>>>(out);

    dim3 pgrid(20, 9);
    precompute_P_kernel<<<pgrid, 128>>>(emb, fl_W1, ft_W1, fp_W1);
    dim3 bgrid(128, 3);
    precompute_B4_kernel<<<bgrid, 32>>>(fl_W2, ft_W2, fp_W2);

    dim3 grid(3, BATCH, 3);  // 1152 CTAs (~4 waves at 2 CTA/SM)
    fused_energy_kernel<<<grid, THREADS, SM_TOTAL>>>(R, seq,
        fl_W1, fl_b1, fl_b2, fl_W3, fl_b3,
        ft_W1, ft_b1, ft_b2, ft_W3, ft_b3,
        fp_W1, fp_b1, fp_b2, fp_W3, fp_b3, out);
}

// round 15
// speedup vs baseline: 2.8728x; 1.3667x over previous
#include <cuda_runtime.h>
#include <cuda_fp16.h>
#include <cuda_bf16.h>
#include <cstdint>

#define HF 128
#define LSEQ 2048
#define BATCH 128
#define CHUNK 704
#define TILE_M 64
#define NTILES 11
#define THREADS 256

#define ASTRIDE 136    // A row stride in fp16 (272B -> ldmatrix conflict-free)
#define B2STRIDE 132   // B image row stride in uint2 (132 mod 16 = 4 -> LDS.64 conflict-free)

// smem byte offsets
#define SM_B2    0                 // 32*132*8 = 33792
#define SM_A     33792             // 64*136*2 = 17408
#define SM_GEO   51200             // 704*2*4 = 5632
#define SM_SEQ   56832             // 708*4 = 2832
#define SM_RED   59664
#define SM_TOTAL 59728

// ---------------- helpers ----------------
__device__ __forceinline__ uint32_t smem_u32(const void* p) {
    uint32_t a;
    asm("{ .reg .u64 t; cvta.to.shared.u64 t, %1; cvt.u32.u64 %0, t; }" : "=r"(a) : "l"(p));
    return a;
}
__device__ __forceinline__ void ldmatrix4(uint32_t a[4], uint32_t addr) {
    asm volatile("ldmatrix.sync.aligned.m8n8.x4.shared.b16 {%0,%1,%2,%3}, [%4];"
                 : "=r"(a[0]), "=r"(a[1]), "=r"(a[2]), "=r"(a[3]) : "r"(addr));
}
__device__ __forceinline__ void mma_f16(float c[4], const uint32_t a[4],
                                        uint32_t b0, uint32_t b1) {
    asm volatile("mma.sync.aligned.m16n8k16.row.col.f32.f16.f16.f32 "
                 "{%0,%1,%2,%3}, {%4,%5,%6,%7}, {%8,%9}, {%0,%1,%2,%3};"
                 : "+f"(c[0]), "+f"(c[1]), "+f"(c[2]), "+f"(c[3])
                 : "r"(a[0]), "r"(a[1]), "r"(a[2]), "r"(a[3]), "r"(b0), "r"(b1));
}
__device__ __forceinline__ uint32_t pack_half(float x, float y) {
    __half2 h = __floats2half2_rn(x, y);
    return *(uint32_t*)&h;
}

// ---------------- globals ----------------
__device__ float g_P[9 * 20 * HF];
__device__ uint2 g_B2[3][32 * B2STRIDE];   // fp16 {b0,b1} frag image

__global__ void zero_out_kernel(float* out) { out[threadIdx.x] = 0.f; }

__global__ void precompute_P_kernel(const float* __restrict__ emb,
                                    const float* __restrict__ W1_0,
                                    const float* __restrict__ W1_1,
                                    const float* __restrict__ W1_2) {
    int aa = blockIdx.x, gk = blockIdx.y, j = threadIdx.x;
    const float* W1; int k, G;
    if (gk < 2)      { W1 = W1_0; k = gk;     G = 1; }
    else if (gk < 5) { W1 = W1_1; k = gk - 2; G = 1; }
    else             { W1 = W1_2; k = gk - 5; G = 2; }
    float s = 0.f;
    #pragma unroll
    for (int c = 0; c < 16; c++)
        s += emb[aa * 16 + c] * W1[(G + k * 16 + c) * HF + j];
    g_P[(gk * 20 + aa) * HF + j] = s;
}

// Per (kt, tig, n): b0 covers k rows {16kt+2tig, +1}, b1 covers {16kt+8+2tig, +1}. fp16.
__global__ void precompute_B2_kernel(const float* __restrict__ W2_0,
                                     const float* __restrict__ W2_1,
                                     const float* __restrict__ W2_2) {
    int n = blockIdx.x, type = blockIdx.y, t = threadIdx.x;  // t 0..31
    const float* W2 = (type == 0) ? W2_0 : (type == 1) ? W2_1 : W2_2;
    int kt = t >> 2, tig = t & 3;
    int kA = 16 * kt + 2 * tig;
    int kB = kA + 8;
    uint2 v;
    v.x = (uint32_t)__half_as_ushort(__float2half_rn(W2[kA * HF + n])) |
          ((uint32_t)__half_as_ushort(__float2half_rn(W2[(kA + 1) * HF + n])) << 16);
    v.y = (uint32_t)__half_as_ushort(__float2half_rn(W2[kB * HF + n])) |
          ((uint32_t)__half_as_ushort(__float2half_rn(W2[(kB + 1) * HF + n])) << 16);
    g_B2[type][t * B2STRIDE + n] = v;
}

// ---------------- main fused kernel ----------------
template <int TYPE, int G, int NE>
__device__ __forceinline__ void run_type(
        char* sm, uint32_t smb,
        const float* __restrict__ R, const int* __restrict__ seq,
        const float* __restrict__ Pg,
        const float* __restrict__ W1, const float* __restrict__ b1,
        const float* __restrict__ b2, const float* __restrict__ W3,
        const float* __restrict__ b3,
        const uint2* __restrict__ B2_g,
        float* __restrict__ out) {
    constexpr int Nelem = LSEQ - 1 - TYPE;

    int*   s_seq = (int*)(sm + SM_SEQ);
    float* s_geo = (float*)(sm + SM_GEO);
    float* s_red = (float*)(sm + SM_RED);
    __half* s_A  = (__half*)(sm + SM_A);
    const uint2* s_B2 = (const uint2*)(sm + SM_B2);

    const int tid  = threadIdx.x;
    const int lane = tid & 31;
    const int wid  = tid >> 5;
    const int mw   = wid >> 2;       // 0..1 : M-half (32 rows each)
    const int nw   = wid & 3;        // 0..3 : N-quarter
    const int gid  = lane >> 2;      // 0..7
    const int tig  = lane & 3;       // 0..3
    const int jp   = tid & 63;       // layer1: column pair {2jp, 2jp+1}
    const int rg   = tid >> 6;       // layer1: row group (16 rows)
    const int b    = blockIdx.y;
    const int cstart = blockIdx.x * CHUNK;

    // ---- B image -> smem ----
    {
        uint2* db = (uint2*)(sm + SM_B2);
        for (int t = tid; t < 32 * B2STRIDE; t += THREADS) db[t] = B2_g[t];
    }
    for (int t = tid; t < CHUNK + 4; t += THREADS) {
        int idx = cstart + t;
        if (idx >= LSEQ) idx = LSEQ - 1;
        s_seq[t] = seq[b * LSEQ + idx];
    }
    const float b1j0 = b1[2 * jp],      b1j1 = b1[2 * jp + 1];
    const float w1a0 = W1[2 * jp],      w1a1 = W1[2 * jp + 1];
    const float w1b0 = (G == 2) ? W1[HF + 2 * jp]     : 0.f;
    const float w1b1 = (G == 2) ? W1[HF + 2 * jp + 1] : 0.f;
    const float b3s  = b3[0];

    // per-thread epilogue coefficients for its 8 columns
    float b2v[8], w3v[8];
    #pragma unroll
    for (int nt = 0; nt < 4; nt++) {
        #pragma unroll
        for (int u = 0; u < 2; u++) {
            int c = nw * 32 + nt * 8 + tig * 2 + u;
            b2v[nt * 2 + u] = __ldg(&b2[c]);
            w3v[nt * 2 + u] = __ldg(&W3[c]);
        }
    }

    // ---- geometry for the whole chunk ----
    const float* Rb = R + (size_t)b * LSEQ * 3;
    for (int t = tid; t < CHUNK; t += THREADS) {
        int i = cstart + t;
        if (i < Nelem) {
            if (TYPE == 0) {
                float dx = __ldg(&Rb[(i + 1) * 3 + 0]) - __ldg(&Rb[i * 3 + 0]);
                float dy = __ldg(&Rb[(i + 1) * 3 + 1]) - __ldg(&Rb[i * 3 + 1]);
                float dz = __ldg(&Rb[(i + 1) * 3 + 2]) - __ldg(&Rb[i * 3 + 2]);
                s_geo[t] = sqrtf(dx * dx + dy * dy + dz * dz);
            } else if (TYPE == 1) {
                float ax = __ldg(&Rb[i * 3 + 0]), ay = __ldg(&Rb[i * 3 + 1]), az = __ldg(&Rb[i * 3 + 2]);
                float bx = __ldg(&Rb[(i + 1) * 3 + 0]), by = __ldg(&Rb[(i + 1) * 3 + 1]), bz = __ldg(&Rb[(i + 1) * 3 + 2]);
                float cx = __ldg(&Rb[(i + 2) * 3 + 0]), cy = __ldg(&Rb[(i + 2) * 3 + 1]), cz = __ldg(&Rb[(i + 2) * 3 + 2]);
                float ux = ax - bx, uy = ay - by, uz = az - bz;
                float vx = cx - bx, vy = cy - by, vz = cz - bz;
                float num = ux * vx + uy * vy + uz * vz;
                float den = sqrtf((ux * ux + uy * uy + uz * uz) * (vx * vx + vy * vy + vz * vz));
                float c = num / den;
                s_geo[t] = fminf(1.f, fmaxf(-1.f, c));
            } else {
                float p0x = __ldg(&Rb[i * 3 + 0]), p0y = __ldg(&Rb[i * 3 + 1]), p0z = __ldg(&Rb[i * 3 + 2]);
                float p1x = __ldg(&Rb[(i + 1) * 3 + 0]), p1y = __ldg(&Rb[(i + 1) * 3 + 1]), p1z = __ldg(&Rb[(i + 1) * 3 + 2]);
                float p2x = __ldg(&Rb[(i + 2) * 3 + 0]), p2y = __ldg(&Rb[(i + 2) * 3 + 1]), p2z = __ldg(&Rb[(i + 2) * 3 + 2]);
                float p3x = __ldg(&Rb[(i + 3) * 3 + 0]), p3y = __ldg(&Rb[(i + 3) * 3 + 1]), p3z = __ldg(&Rb[(i + 3) * 3 + 2]);
                float b1x = p1x - p0x, b1y = p1y - p0y, b1z = p1z - p0z;
                float b2x = p2x - p1x, b2y = p2y - p1y, b2z = p2z - p1z;
                float b3x = p3x - p2x, b3y = p3y - p2y, b3z = p3z - p2z;
                float n1x = b1y * b2z - b1z * b2y, n1y = b1z * b2x - b1x * b2z, n1z = b1x * b2y - b1y * b2x;
                float n2x = b2y * b3z - b2z * b3y, n2y = b2z * b3x - b2x * b3z, n2z = b2x * b3y - b2y * b3x;
                float inv = rsqrtf(b2x * b2x + b2y * b2y + b2z * b2z);
                float ux = b2x * inv, uy = b2y * inv, uz = b2z * inv;
                float m1x = n1y * uz - n1z * uy, m1y = n1z * ux - n1x * uz, m1z = n1x * uy - n1y * ux;
                float yv = m1x * n2x + m1y * n2y + m1z * n2z;
                float xv = n1x * n2x + n1y * n2y + n1z * n2z;
                float rn = rsqrtf(xv * xv + yv * yv);
                s_geo[t * 2 + 0] = yv * rn;
                s_geo[t * 2 + 1] = xv * rn;
            }
        } else {
            if (G == 1) s_geo[t] = 0.f;
            else { s_geo[t * 2 + 0] = 0.f; s_geo[t * 2 + 1] = 0.f; }
        }
    }
    __syncthreads();

    // ldmatrix per-thread base byte offset into A
    const uint32_t a_off = (uint32_t)((mw * 32 + (lane & 15)) * ASTRIDE + (lane >> 4) * 8) * 2;
    const uint32_t abase = smb + SM_A + a_off;

    uint32_t hpk[16];   // staged packed-fp16 h1 pairs for 16 rows

    // ---- layer1 compute into registers (LDG.64 pairs; overlaps MMA) ----
    auto layer1_regs = [&](int tile) {
        const int li0 = tile * TILE_M + rg * 16;
        float a0[16], a1[16];
        #pragma unroll
        for (int e = 0; e < 16; e++) {
            const int li = li0 + e;
            a0[e] = b1j0; a1[e] = b1j1;
            if (G == 2) {
                float2 sc = ((const float2*)s_geo)[li];
                a0[e] = fmaf(sc.x, w1a0, fmaf(sc.y, w1b0, a0[e]));
                a1[e] = fmaf(sc.x, w1a1, fmaf(sc.y, w1b1, a1[e]));
            } else {
                float g = s_geo[li];
                a0[e] = fmaf(g, w1a0, a0[e]);
                a1[e] = fmaf(g, w1a1, a1[e]);
            }
        }
        // k-major: batch 16 independent LDG.64 per k-step, then consume
        #pragma unroll
        for (int k = 0; k < NE; k++) {
            float2 p[16];
            #pragma unroll
            for (int e = 0; e < 16; e++)
                p[e] = __ldg((const float2*)&Pg[(k * 20 + s_seq[li0 + e + k]) * HF + 2 * jp]);
            #pragma unroll
            for (int e = 0; e < 16; e++) { a0[e] += p[e].x; a1[e] += p[e].y; }
        }
        #pragma unroll
        for (int e = 0; e < 16; e++)
            hpk[e] = pack_half(fmaxf(a0[e], 0.f), fmaxf(a1[e], 0.f));
    };
    // ---- store staged h1 to A smem ----
    auto store_A = [&]() {
        #pragma unroll
        for (int e = 0; e < 16; e++) {
            int row = rg * 16 + e;
            *(uint32_t*)&s_A[row * ASTRIDE + 2 * jp] = hpk[e];
        }
    };

    float thread_sum = 0.f;

    layer1_regs(0);
    store_A();
    __syncthreads();

    for (int tile = 0; tile < NTILES; tile++) {
        // stage next tile's h1 (LDGs overlap the MMA below)
        if (tile + 1 < NTILES) layer1_regs(tile + 1);

        // ---- single-pass fp16 MMA: C = A * B ----
        float c[2][4][4];
        #pragma unroll
        for (int mt = 0; mt < 2; mt++)
            #pragma unroll
            for (int nt = 0; nt < 4; nt++)
                #pragma unroll
                for (int q = 0; q < 4; q++) c[mt][nt][q] = 0.f;

        #pragma unroll
        for (int kt = 0; kt < 8; kt++) {
            uint2 bb[4];
            #pragma unroll
            for (int nt = 0; nt < 4; nt++)
                bb[nt] = s_B2[(kt * 4 + tig) * B2STRIDE + nw * 32 + nt * 8 + gid];
            uint32_t ah[2][4];
            #pragma unroll
            for (int mt = 0; mt < 2; mt++)
                ldmatrix4(ah[mt], abase + (uint32_t)(mt * 16 * ASTRIDE * 2 + kt * 32));
            #pragma unroll
            for (int mt = 0; mt < 2; mt++)
                #pragma unroll
                for (int nt = 0; nt < 4; nt++)
                    mma_f16(c[mt][nt], ah[mt], bb[nt].x, bb[nt].y);
        }

        // ---- epilogue: sum relu(D + b2)*w3 over valid rows ----
        {
            const int e0 = cstart + tile * TILE_M + mw * 32;
            #pragma unroll
            for (int mt = 0; mt < 2; mt++) {
                const int r0 = mt * 16 + gid;
                const bool v0 = (e0 + r0) < Nelem;
                const bool v1 = (e0 + r0 + 8) < Nelem;
                float p0 = 0.f, p1 = 0.f;
                #pragma unroll
                for (int nt = 0; nt < 4; nt++) {
                    p0 += fmaxf(c[mt][nt][0] + b2v[nt * 2 + 0], 0.f) * w3v[nt * 2 + 0]
                        + fmaxf(c[mt][nt][1] + b2v[nt * 2 + 1], 0.f) * w3v[nt * 2 + 1];
                    p1 += fmaxf(c[mt][nt][2] + b2v[nt * 2 + 0], 0.f) * w3v[nt * 2 + 0]
                        + fmaxf(c[mt][nt][3] + b2v[nt * 2 + 1], 0.f) * w3v[nt * 2 + 1];
                }
                thread_sum += (v0 ? p0 : 0.f) + (v1 ? p1 : 0.f);
            }
        }

        if (tile + 1 < NTILES) {
            __syncthreads();   // all warps done reading A
            store_A();
            __syncthreads();   // A ready for next MMA
        }
    }

    // ---- final reduction ----
    #pragma unroll
    for (int off = 16; off; off >>= 1)
        thread_sum += __shfl_xor_sync(0xffffffffu, thread_sum, off);
    if (lane == 0) s_red[wid] = thread_sum;
    __syncthreads();
    if (tid == 0) {
        int count = Nelem - cstart;
        if (count > CHUNK) count = CHUNK;
        if (count < 0) count = 0;
        float total = 0.f;
        #pragma unroll
        for (int w = 0; w < 8; w++) total += s_red[w];
        atomicAdd(&out[b], total + (float)count * b3s);
    }
}

__global__ __launch_bounds__(THREADS, 2)
void fused_energy_kernel(const float* __restrict__ R, const int* __restrict__ seq,
                         const float* fl_W1, const float* fl_b1, const float* fl_b2,
                         const float* fl_W3, const float* fl_b3,
                         const float* ft_W1, const float* ft_b1, const float* ft_b2,
                         const float* ft_W3, const float* ft_b3,
                         const float* fp_W1, const float* fp_b1, const float* fp_b2,
                         const float* fp_W3, const float* fp_b3,
                         float* __restrict__ out) {
    extern __shared__ char sm[];
    uint32_t smb = smem_u32(sm);
    if (blockIdx.z == 0) {
        run_type<0, 1, 2>(sm, smb, R, seq, g_P + 0 * 20 * HF,
                          fl_W1, fl_b1, fl_b2, fl_W3, fl_b3, g_B2[0], out);
    } else if (blockIdx.z == 1) {
        run_type<1, 1, 3>(sm, smb, R, seq, g_P + 2 * 20 * HF,
                          ft_W1, ft_b1, ft_b2, ft_W3, ft_b3, g_B2[1], out);
    } else {
        run_type<2, 2, 4>(sm, smb, R, seq, g_P + 5 * 20 * HF,
                          fp_W1, fp_b1, fp_b2, fp_W3, fp_b3, g_B2[2], out);
    }
}

extern "C" void kernel_launch(void* const* d_in, const int* in_sizes, int n_in,
                              void* d_out, int out_size) {
    const float* R   = (const float*)d_in[0];
    const int*   seq = (const int*)d_in[1];
    const float* emb = (const float*)d_in[2];
    const float* fl_W1 = (const float*)d_in[3];
    const float* fl_b1 = (const float*)d_in[4];
    const float* fl_W2 = (const float*)d_in[5];
    const float* fl_b2 = (const float*)d_in[6];
    const float* fl_W3 = (const float*)d_in[7];
    const float* fl_b3 = (const float*)d_in[8];
    const float* ft_W1 = (const float*)d_in[9];
    const float* ft_b1 = (const float*)d_in[10];
    const float* ft_W2 = (const float*)d_in[11];
    const float* ft_b2 = (const float*)d_in[12];
    const float* ft_W3 = (const float*)d_in[13];
    const float* ft_b3 = (const float*)d_in[14];
    const float* fp_W1 = (const float*)d_in[15];
    const float* fp_b1 = (const float*)d_in[16];
    const float* fp_W2 = (const float*)d_in[17];
    const float* fp_b2 = (const float*)d_in[18];
    const float* fp_W3 = (const float*)d_in[19];
    const float* fp_b3 = (const float*)d_in[20];
    float* out = (float*)d_out;

    cudaFuncSetAttribute(fused_energy_kernel,
                         cudaFuncAttributeMaxDynamicSharedMemorySize, SM_TOTAL);

    zero_out_kernel<<<1, 128>>>(out);

    dim3 pgrid(20, 9);
    precompute_P_kernel<<<pgrid, 128>>>(emb, fl_W1, ft_W1, fp_W1);
    dim3 bgrid(128, 3);
    precompute_B2_kernel<<<bgrid, 32>>>(fl_W2, ft_W2, fp_W2);

    dim3 grid(3, BATCH, 3);  // 1152 CTAs (~4 waves at 2 CTA/SM)
    fused_energy_kernel<<<grid, THREADS, SM_TOTAL>>>(R, seq,
        fl_W1, fl_b1, fl_b2, fl_W3, fl_b3,
        ft_W1, ft_b1, ft_b2, ft_W3, ft_b3,
        fp_W1, fp_b1, fp_b2, fp_W3, fp_b3, out);
}